// round 1
// baseline (speedup 1.0000x reference)
#include <cuda_runtime.h>
#include <math.h>

#define NN 100000
#define EE 1600000
#define CC 64
#define RR 20
#define LL 3
#define NB_SCAN 98   // ceil(100000/1024)

// ---------------- scratch (static device globals; no allocation) ----------------
__device__ float d_hA[NN * CC];
__device__ float d_hB[NN * CC];
__device__ float d_hp[NN * CC];
__device__ float d_asrc[NN];
__device__ float d_adst[NN];
__device__ float d_escratch[EE];
__device__ int   d_deg[NN];
__device__ int   d_cursor[NN];
__device__ int   d_rowptr[NN + 1];
__device__ int   d_adj[EE];
__device__ int   d_bsum[128];
__device__ float d_part[2048];
__device__ float d_relatt[LL * RR];
__device__ float d_stats[LL * 2];   // per layer: mu, 1/(std+eps)

__device__ __forceinline__ const float* layer_in(int l)  { return (l & 1) ? d_hB : d_hA; }
__device__ __forceinline__ float*       layer_out(int l) { return (l & 1) ? d_hA : d_hB; }

// ---------------- CSR build ----------------
__global__ void k_zero() {
    int i = blockIdx.x * 256 + threadIdx.x;
    if (i < NN) { d_deg[i] = 0; d_cursor[i] = 0; }
}

__global__ void k_deg(const int* __restrict__ ei) {
    int e = blockIdx.x * 256 + threadIdx.x;
    if (e < EE) atomicAdd(&d_deg[ei[EE + e]], 1);
}

__global__ void k_scan1() {
    __shared__ int tmp[1024];
    int i = blockIdx.x * 1024 + threadIdx.x;
    int v = (i < NN) ? d_deg[i] : 0;
    tmp[threadIdx.x] = v;
    __syncthreads();
    for (int off = 1; off < 1024; off <<= 1) {
        int t = (threadIdx.x >= off) ? tmp[threadIdx.x - off] : 0;
        __syncthreads();
        tmp[threadIdx.x] += t;
        __syncthreads();
    }
    if (i < NN) d_rowptr[i] = tmp[threadIdx.x] - v;      // exclusive
    if (threadIdx.x == 1023) d_bsum[blockIdx.x] = tmp[1023];
}

__global__ void k_scan2() {
    int tid = threadIdx.x;
    int v = (tid < NB_SCAN) ? d_bsum[tid] : 0;
    int orig = v;
    int lane = tid & 31, w = tid >> 5;
    for (int o = 1; o < 32; o <<= 1) {
        int t = __shfl_up_sync(0xffffffffu, v, o);
        if (lane >= o) v += t;
    }
    __shared__ int ws[4];
    if (lane == 31) ws[w] = v;
    __syncthreads();
    for (int k = 0; k < w; k++) v += ws[k];
    if (tid < NB_SCAN) d_bsum[tid] = v - orig;           // exclusive block offsets
}

__global__ void k_scan3() {
    int i = blockIdx.x * 1024 + threadIdx.x;
    if (i < NN) d_rowptr[i] += d_bsum[blockIdx.x];
    if (i == 0) d_rowptr[NN] = EE;
}

__global__ void k_fill(const int* __restrict__ ei, const int* __restrict__ et) {
    int e = blockIdx.x * 256 + threadIdx.x;
    if (e < EE) {
        int s = ei[e];
        int d = ei[EE + e];
        int t = et[e];
        int pos = d_rowptr[d] + atomicAdd(&d_cursor[d], 1);
        d_adj[pos] = s | (t << 20);                      // src<2^20, type<32
    }
}

// ---------------- per-(layer,relation) edge-attention scalar ----------------
__global__ void k_relatt(const float* __restrict__ lin_edge,
                         const float* __restrict__ att_edge,
                         const float* __restrict__ edge_emb) {
    int l = blockIdx.x / RR, r = blockIdx.x % RR;
    int j = threadIdx.x;                                 // 64 threads
    const float* We  = lin_edge + l * 8 * CC;
    const float* emb = edge_emb + (l * RR + r) * 8;
    float t = 0.f;
#pragma unroll
    for (int d = 0; d < 8; d++) t += emb[d] * We[d * CC + j];
    t *= att_edge[l * CC + j];
    for (int o = 16; o; o >>= 1) t += __shfl_xor_sync(0xffffffffu, t, o);
    __shared__ float rs[2];
    if ((j & 31) == 0) rs[j >> 5] = t;
    __syncthreads();
    if (j == 0) d_relatt[l * RR + r] = rs[0] + rs[1];
}

// ---------------- h0 = broadcast(x) ----------------
__global__ void k_init_h(const float* __restrict__ x) {
    int i = blockIdx.x * 256 + threadIdx.x;              // float4 index
    float v = x[i >> 4];
    ((float4*)d_hA)[i] = make_float4(v, v, v, v);
}

// ---------------- hp = h @ W ; alpha_src/dst = hp @ a_{s,d} ----------------
__global__ __launch_bounds__(256) void k_gemm_alpha(int layer,
        const float* __restrict__ Wl,
        const float* __restrict__ as_g,
        const float* __restrict__ ad_g) {
    __shared__ float Ws[64 * 64];
    __shared__ float hs[32 * 65];
    const float* hin = layer_in(layer);
    int tid = threadIdx.x;
    const float4* W4 = (const float4*)Wl;
#pragma unroll
    for (int i = tid; i < 1024; i += 256) ((float4*)Ws)[i] = W4[i];
    int base = blockIdx.x * 32;
#pragma unroll
    for (int i = tid; i < 2048; i += 256) {
        int nl = i >> 6, k = i & 63;
        hs[nl * 65 + k] = hin[base * 64 + i];
    }
    __syncthreads();

    int g = tid & 15, slot = tid >> 4;
    int j = g * 4;
    float4 a0 = make_float4(0.f, 0.f, 0.f, 0.f);
    float4 a1 = a0;
#pragma unroll
    for (int k = 0; k < 64; k++) {
        float4 w = *(const float4*)&Ws[k * 64 + j];
        float h0 = hs[slot * 65 + k];
        float h1 = hs[(slot + 16) * 65 + k];
        a0.x += h0 * w.x; a0.y += h0 * w.y; a0.z += h0 * w.z; a0.w += h0 * w.w;
        a1.x += h1 * w.x; a1.y += h1 * w.y; a1.z += h1 * w.z; a1.w += h1 * w.w;
    }
    int n0 = base + slot, n1 = base + slot + 16;
    *(float4*)&d_hp[n0 * 64 + j] = a0;
    *(float4*)&d_hp[n1 * 64 + j] = a1;

    float4 as4 = *(const float4*)&as_g[j];
    float4 ad4 = *(const float4*)&ad_g[j];
    float ps0 = a0.x * as4.x + a0.y * as4.y + a0.z * as4.z + a0.w * as4.w;
    float pd0 = a0.x * ad4.x + a0.y * ad4.y + a0.z * ad4.z + a0.w * ad4.w;
    float ps1 = a1.x * as4.x + a1.y * as4.y + a1.z * as4.z + a1.w * as4.w;
    float pd1 = a1.x * ad4.x + a1.y * ad4.y + a1.z * ad4.z + a1.w * ad4.w;
#pragma unroll
    for (int o = 8; o; o >>= 1) {
        ps0 += __shfl_down_sync(0xffffffffu, ps0, o, 16);
        pd0 += __shfl_down_sync(0xffffffffu, pd0, o, 16);
        ps1 += __shfl_down_sync(0xffffffffu, ps1, o, 16);
        pd1 += __shfl_down_sync(0xffffffffu, pd1, o, 16);
    }
    if (g == 0) {
        d_asrc[n0] = ps0; d_adst[n0] = pd0;
        d_asrc[n1] = ps1; d_adst[n1] = pd1;
    }
}

// ---------------- warp-per-dst-node GAT aggregation (softmax + weighted sum) --
__global__ __launch_bounds__(256) void k_agg(int layer, const float* __restrict__ bias,
                                             int use_skip) {
    int wid  = (blockIdx.x * 256 + threadIdx.x) >> 5;   // node id
    int lane = threadIdx.x & 31;
    if (wid >= NN) return;
    int start = d_rowptr[wid], end = d_rowptr[wid + 1];
    float ad = d_adst[wid];

    // pass 1: leaky logits + warp max
    float m = -1e30f;
    for (int i = start + lane; i < end; i += 32) {
        int p = d_adj[i];
        int s = p & 0xFFFFF;
        int t = p >> 20;
        float l = d_asrc[s] + ad + d_relatt[layer * RR + t];
        l = (l > 0.f) ? l : 0.2f * l;
        d_escratch[i] = l;
        m = fmaxf(m, l);
    }
    for (int o = 16; o; o >>= 1) m = fmaxf(m, __shfl_xor_sync(0xffffffffu, m, o));
    __syncwarp();

    // pass 2: exp + warp sum
    float den = 0.f;
    for (int i = start + lane; i < end; i += 32) {
        float ex = expf(d_escratch[i] - m);
        d_escratch[i] = ex;
        den += ex;
    }
    for (int o = 16; o; o >>= 1) den += __shfl_xor_sync(0xffffffffu, den, o);
    __syncwarp();
    float inv = 1.f / (den + 1e-16f);

    // pass 3: weighted gather of hp rows (lane = 2 channels)
    int c = lane * 2;
    float ax = 0.f, ay = 0.f;
    for (int i = start; i < end; i++) {
        int p = d_adj[i];
        int s = p & 0xFFFFF;
        float coef = d_escratch[i] * inv;
        float2 v = *(const float2*)&d_hp[s * 64 + c];
        ax += v.x * coef;
        ay += v.y * coef;
    }
    float ox = ax + bias[c], oy = ay + bias[c + 1];
    if (use_skip) {
        const float* xl = layer_in(layer);
        ox += xl[wid * 64 + c];
        oy += xl[wid * 64 + c + 1];
    }
    float* hout = layer_out(layer);
    *(float2*)&hout[wid * 64 + c] = make_float2(ox, oy);
}

// ---------------- graph LayerNorm: two-stage reduce + normalize ----------------
__global__ void k_lnred1(int layer) {
    const float4* h4 = (const float4*)layer_out(layer);
    float s = 0.f, ss = 0.f;
    for (int i = blockIdx.x * 256 + threadIdx.x; i < NN * CC / 4; i += 1024 * 256) {
        float4 v = h4[i];
        s  += v.x + v.y + v.z + v.w;
        ss += v.x * v.x + v.y * v.y + v.z * v.z + v.w * v.w;
    }
    for (int o = 16; o; o >>= 1) {
        s  += __shfl_xor_sync(0xffffffffu, s, o);
        ss += __shfl_xor_sync(0xffffffffu, ss, o);
    }
    __shared__ float sh[8][2];
    int w = threadIdx.x >> 5, lane = threadIdx.x & 31;
    if (lane == 0) { sh[w][0] = s; sh[w][1] = ss; }
    __syncthreads();
    if (threadIdx.x == 0) {
        float ts = 0.f, tss = 0.f;
        for (int k = 0; k < 8; k++) { ts += sh[k][0]; tss += sh[k][1]; }
        d_part[blockIdx.x * 2]     = ts;
        d_part[blockIdx.x * 2 + 1] = tss;
    }
}

__global__ void k_lnred2(int layer) {
    int tid = threadIdx.x;                               // 1024 threads
    float s = d_part[2 * tid], ss = d_part[2 * tid + 1];
    for (int o = 16; o; o >>= 1) {
        s  += __shfl_xor_sync(0xffffffffu, s, o);
        ss += __shfl_xor_sync(0xffffffffu, ss, o);
    }
    __shared__ float sh[32][2];
    int w = tid >> 5, lane = tid & 31;
    if (lane == 0) { sh[w][0] = s; sh[w][1] = ss; }
    __syncthreads();
    if (w == 0) {
        s  = sh[lane][0];
        ss = sh[lane][1];
        for (int o = 16; o; o >>= 1) {
            s  += __shfl_xor_sync(0xffffffffu, s, o);
            ss += __shfl_xor_sync(0xffffffffu, ss, o);
        }
        if (lane == 0) {
            const float M = (float)(NN * CC);
            float mu  = s / M;
            float var = ss / M - mu * mu;
            var = var > 0.f ? var : 0.f;
            d_stats[layer * 2]     = mu;
            d_stats[layer * 2 + 1] = 1.f / (sqrtf(var) + 1e-5f);
        }
    }
}

__global__ void k_norm(int layer, const float* __restrict__ lnw, const float* __restrict__ lnb) {
    int i = blockIdx.x * 256 + threadIdx.x;              // float4 index
    float mu = d_stats[layer * 2], inv = d_stats[layer * 2 + 1];
    int c = (i * 4) & 63;
    float4* h4 = (float4*)layer_out(layer);
    float4 v = h4[i];
    v.x = fmaxf((v.x - mu) * inv * lnw[c]     + lnb[c],     0.f);
    v.y = fmaxf((v.y - mu) * inv * lnw[c + 1] + lnb[c + 1], 0.f);
    v.z = fmaxf((v.z - mu) * inv * lnw[c + 2] + lnb[c + 2], 0.f);
    v.w = fmaxf((v.w - mu) * inv * lnw[c + 3] + lnb[c + 3], 0.f);
    h4[i] = v;
}

// ---------------- output MLP + sigmoid ----------------
__global__ __launch_bounds__(256) void k_mlp(const float* __restrict__ w1,
        const float* __restrict__ b1, const float* __restrict__ w2,
        const float* __restrict__ b2, float* __restrict__ out) {
    __shared__ float w1s[64 * 100];
    __shared__ float b1s[100];
    __shared__ float w2s[100];
    int tid = threadIdx.x;
    for (int i = tid; i < 6400; i += 256) w1s[i] = w1[i];
    if (tid < 100) { b1s[tid] = b1[tid]; w2s[tid] = w2[tid]; }
    __syncthreads();
    int n = blockIdx.x * 256 + tid;
    if (n >= NN) return;
    const float* h = d_hB;                               // layer_out(2)
    float hr[64];
#pragma unroll
    for (int k = 0; k < 64; k++) hr[k] = h[n * 64 + k];
    float z = 0.f;
    for (int j = 0; j < 100; j++) {
        float a = b1s[j];
#pragma unroll
        for (int k = 0; k < 64; k++) a += hr[k] * w1s[k * 100 + j];
        z += fmaxf(a, 0.f) * w2s[j];
    }
    z += b2[0];
    out[n] = 1.f / (1.f + expf(-z));
}

// ---------------- launch ----------------
extern "C" void kernel_launch(void* const* d_in, const int* in_sizes, int n_in,
                              void* d_out, int out_size) {
    const float* x         = (const float*)d_in[0];
    const int*   ei        = (const int*)  d_in[1];
    const int*   et        = (const int*)  d_in[2];
    const float* W         = (const float*)d_in[3];
    const float* att_src   = (const float*)d_in[4];
    const float* att_dst   = (const float*)d_in[5];
    const float* lin_edge  = (const float*)d_in[6];
    const float* att_edge  = (const float*)d_in[7];
    const float* conv_bias = (const float*)d_in[8];
    const float* edge_emb  = (const float*)d_in[9];
    const float* ln_w      = (const float*)d_in[10];
    const float* ln_b      = (const float*)d_in[11];
    const float* w1        = (const float*)d_in[12];
    const float* b1        = (const float*)d_in[13];
    const float* w2        = (const float*)d_in[14];
    const float* b2        = (const float*)d_in[15];
    float* out = (float*)d_out;

    // CSR build (edges identical across layers -> once per call)
    k_zero<<<(NN + 255) / 256, 256>>>();
    k_deg<<<EE / 256, 256>>>(ei);
    k_scan1<<<NB_SCAN, 1024>>>();
    k_scan2<<<1, 128>>>();
    k_scan3<<<NB_SCAN, 1024>>>();
    k_fill<<<EE / 256, 256>>>(ei, et);
    k_relatt<<<LL * RR, 64>>>(lin_edge, att_edge, edge_emb);
    k_init_h<<<NN * CC / 4 / 256, 256>>>(x);

    for (int l = 0; l < LL; l++) {
        k_gemm_alpha<<<NN / 32, 256>>>(l, W + l * CC * CC,
                                       att_src + l * CC, att_dst + l * CC);
        k_agg<<<NN / 8, 256>>>(l, conv_bias + l * CC, l > 0 ? 1 : 0);
        k_lnred1<<<1024, 256>>>(l);
        k_lnred2<<<1, 1024>>>(l);
        k_norm<<<NN * CC / 4 / 256, 256>>>(l, ln_w, ln_b);
    }
    k_mlp<<<(NN + 255) / 256, 256>>>(w1, b1, w2, b2, out);
}

// round 2
// speedup vs baseline: 1.1234x; 1.1234x over previous
#include <cuda_runtime.h>
#include <cuda_fp16.h>
#include <math.h>

#define NN 100000
#define EE 1600000
#define CC 64
#define RR 20
#define LL 3
#define NB_SCAN 98        // ceil(100000/1024)
#define NAGG_BLK 12500    // NN/8

// ---------------- scratch (static device globals; no allocation) ----------------
__device__ float  d_b0[NN * CC];
__device__ float  d_b1[NN * CC];
__device__ float  d_b2[NN * CC];
__device__ __half2 d_hph[NN * 32];   // hp in fp16, row = 32 half2 = 64 ch
__device__ float  d_asrc[NN];
__device__ float  d_adst[NN];
__device__ float  d_escratch[EE];
__device__ int    d_deg[NN];
__device__ int    d_cursor[NN];
__device__ int    d_rowptr[NN + 1];
__device__ int    d_adj[EE];
__device__ int    d_bsum[128];
__device__ float  d_part[NAGG_BLK * 2];
__device__ float  d_relatt[LL * RR];
__device__ float  d_stats[LL * 2];   // per layer: mu, 1/(std+eps)
__device__ float  d_colsum[CC];      // layer-0: column sums of W0
__device__ float  d_l0s[2];          // layer-0: colsum·a_src, colsum·a_dst

__device__ __forceinline__ float* buf(int l) {
    return l == 0 ? d_b0 : (l == 1 ? d_b1 : d_b2);
}

// ---------------- CSR build ----------------
__global__ void k_zero() {
    int i = blockIdx.x * 256 + threadIdx.x;
    if (i < NN) { d_deg[i] = 0; d_cursor[i] = 0; }
}

__global__ void k_deg(const int* __restrict__ ei) {
    int e = blockIdx.x * 256 + threadIdx.x;
    if (e < EE) atomicAdd(&d_deg[ei[EE + e]], 1);
}

__global__ void k_scan1() {
    __shared__ int tmp[1024];
    int i = blockIdx.x * 1024 + threadIdx.x;
    int v = (i < NN) ? d_deg[i] : 0;
    tmp[threadIdx.x] = v;
    __syncthreads();
    for (int off = 1; off < 1024; off <<= 1) {
        int t = (threadIdx.x >= off) ? tmp[threadIdx.x - off] : 0;
        __syncthreads();
        tmp[threadIdx.x] += t;
        __syncthreads();
    }
    if (i < NN) d_rowptr[i] = tmp[threadIdx.x] - v;      // exclusive
    if (threadIdx.x == 1023) d_bsum[blockIdx.x] = tmp[1023];
}

__global__ void k_scan2() {
    int tid = threadIdx.x;
    int v = (tid < NB_SCAN) ? d_bsum[tid] : 0;
    int orig = v;
    int lane = tid & 31, w = tid >> 5;
    for (int o = 1; o < 32; o <<= 1) {
        int t = __shfl_up_sync(0xffffffffu, v, o);
        if (lane >= o) v += t;
    }
    __shared__ int ws[4];
    if (lane == 31) ws[w] = v;
    __syncthreads();
    for (int k = 0; k < w; k++) v += ws[k];
    if (tid < NB_SCAN) d_bsum[tid] = v - orig;           // exclusive block offsets
}

__global__ void k_scan3() {
    int i = blockIdx.x * 1024 + threadIdx.x;
    if (i < NN) d_rowptr[i] += d_bsum[blockIdx.x];
    if (i == 0) d_rowptr[NN] = EE;
}

__global__ void k_fill(const int* __restrict__ ei, const int* __restrict__ et) {
    int e = blockIdx.x * 256 + threadIdx.x;
    if (e < EE) {
        int s = ei[e];
        int d = ei[EE + e];
        int t = et[e];
        int pos = d_rowptr[d] + atomicAdd(&d_cursor[d], 1);
        d_adj[pos] = s | (t << 20);                      // src<2^20, type<32
    }
}

// ---------------- relation-attention scalars + layer-0 prep ----------------
__global__ void k_relprep(const float* __restrict__ lin_edge,
                          const float* __restrict__ att_edge,
                          const float* __restrict__ edge_emb,
                          const float* __restrict__ W,
                          const float* __restrict__ att_src,
                          const float* __restrict__ att_dst) {
    int j = threadIdx.x;                                 // 64 threads
    if (blockIdx.x < LL * RR) {
        int l = blockIdx.x / RR, r = blockIdx.x % RR;
        const float* We  = lin_edge + l * 8 * CC;
        const float* emb = edge_emb + (l * RR + r) * 8;
        float t = 0.f;
#pragma unroll
        for (int d = 0; d < 8; d++) t += emb[d] * We[d * CC + j];
        t *= att_edge[l * CC + j];
        for (int o = 16; o; o >>= 1) t += __shfl_xor_sync(0xffffffffu, t, o);
        __shared__ float rs[2];
        if ((j & 31) == 0) rs[j >> 5] = t;
        __syncthreads();
        if (j == 0) d_relatt[l * RR + r] = rs[0] + rs[1];
    } else {
        // layer-0 prep: colsum_j = sum_k W0[k][j]; scalars = colsum·a_{s,d}
        float cs = 0.f;
#pragma unroll
        for (int k = 0; k < CC; k++) cs += W[k * CC + j];
        d_colsum[j] = cs;
        float s1 = cs * att_src[j];
        float s2 = cs * att_dst[j];
        for (int o = 16; o; o >>= 1) {
            s1 += __shfl_xor_sync(0xffffffffu, s1, o);
            s2 += __shfl_xor_sync(0xffffffffu, s2, o);
        }
        __shared__ float r1[2], r2[2];
        if ((j & 31) == 0) { r1[j >> 5] = s1; r2[j >> 5] = s2; }
        __syncthreads();
        if (j == 0) { d_l0s[0] = r1[0] + r1[1]; d_l0s[1] = r2[0] + r2[1]; }
    }
}

// ---------------- layer-0 "gemm": hp = outer(x, colsum) ----------------
__global__ void k_l0(const float* __restrict__ x) {
    int i = blockIdx.x * 256 + threadIdx.x;              // half2 slot over NN*32
    int n = i >> 5, c2 = i & 31;
    float v = x[n];
    d_hph[i] = __floats2half2_rn(v * d_colsum[c2 * 2], v * d_colsum[c2 * 2 + 1]);
    if (i < NN) {
        float xv = x[i];
        d_asrc[i] = xv * d_l0s[0];
        d_adst[i] = xv * d_l0s[1];
    }
}

// ---- hp = norm(h) @ W (fp16 out) ; alpha_src/dst = hp @ a_{s,d} (layers 1,2) ----
__global__ __launch_bounds__(256) void k_gemm_alpha(int layer,
        const float* __restrict__ Wl,
        const float* __restrict__ as_g,
        const float* __restrict__ ad_g,
        const float* __restrict__ lnw,
        const float* __restrict__ lnb) {
    __shared__ float Ws[64 * 64];
    __shared__ float hs[32 * 65];
    __shared__ float lnw_s[64], lnb_s[64];
    const float* hin = buf(layer - 1);
    float mu  = d_stats[(layer - 1) * 2];
    float inv = d_stats[(layer - 1) * 2 + 1];
    int tid = threadIdx.x;
    if (tid < 64) { lnw_s[tid] = lnw[tid]; lnb_s[tid] = lnb[tid]; }
    const float4* W4 = (const float4*)Wl;
#pragma unroll
    for (int i = tid; i < 1024; i += 256) ((float4*)Ws)[i] = W4[i];
    __syncthreads();
    int base = blockIdx.x * 32;
#pragma unroll
    for (int i = tid; i < 2048; i += 256) {
        int nl = i >> 6, k = i & 63;
        float raw = hin[base * 64 + i];
        hs[nl * 65 + k] = fmaxf((raw - mu) * inv * lnw_s[k] + lnb_s[k], 0.f);
    }
    __syncthreads();

    int g = tid & 15, slot = tid >> 4;
    int j = g * 4;
    float4 a0 = make_float4(0.f, 0.f, 0.f, 0.f);
    float4 a1 = a0;
#pragma unroll
    for (int k = 0; k < 64; k++) {
        float4 w = *(const float4*)&Ws[k * 64 + j];
        float h0 = hs[slot * 65 + k];
        float h1 = hs[(slot + 16) * 65 + k];
        a0.x += h0 * w.x; a0.y += h0 * w.y; a0.z += h0 * w.z; a0.w += h0 * w.w;
        a1.x += h1 * w.x; a1.y += h1 * w.y; a1.z += h1 * w.z; a1.w += h1 * w.w;
    }
    int n0 = base + slot, n1 = base + slot + 16;
    {
        __half2 p0 = __floats2half2_rn(a0.x, a0.y);
        __half2 p1 = __floats2half2_rn(a0.z, a0.w);
        *(uint2*)&d_hph[n0 * 32 + g * 2] = make_uint2(*(unsigned*)&p0, *(unsigned*)&p1);
        __half2 q0 = __floats2half2_rn(a1.x, a1.y);
        __half2 q1 = __floats2half2_rn(a1.z, a1.w);
        *(uint2*)&d_hph[n1 * 32 + g * 2] = make_uint2(*(unsigned*)&q0, *(unsigned*)&q1);
    }

    float4 as4 = *(const float4*)&as_g[j];
    float4 ad4 = *(const float4*)&ad_g[j];
    float ps0 = a0.x * as4.x + a0.y * as4.y + a0.z * as4.z + a0.w * as4.w;
    float pd0 = a0.x * ad4.x + a0.y * ad4.y + a0.z * ad4.z + a0.w * ad4.w;
    float ps1 = a1.x * as4.x + a1.y * as4.y + a1.z * as4.z + a1.w * as4.w;
    float pd1 = a1.x * ad4.x + a1.y * ad4.y + a1.z * ad4.z + a1.w * ad4.w;
#pragma unroll
    for (int o = 8; o; o >>= 1) {
        ps0 += __shfl_down_sync(0xffffffffu, ps0, o, 16);
        pd0 += __shfl_down_sync(0xffffffffu, pd0, o, 16);
        ps1 += __shfl_down_sync(0xffffffffu, ps1, o, 16);
        pd1 += __shfl_down_sync(0xffffffffu, pd1, o, 16);
    }
    if (g == 0) {
        d_asrc[n0] = ps0; d_adst[n0] = pd0;
        d_asrc[n1] = ps1; d_adst[n1] = pd1;
    }
}

// ------- warp-per-dst GAT aggregation + fused LN partial reduction -------
__global__ __launch_bounds__(256) void k_agg(int layer, const float* __restrict__ bias,
                                             const float* __restrict__ lnw,
                                             const float* __restrict__ lnb,
                                             int use_skip) {
    __shared__ float rel_s[RR];
    __shared__ float lnw_s[64], lnb_s[64];
    __shared__ float red[8][2];
    int tid = threadIdx.x;
    if (tid < RR) rel_s[tid] = d_relatt[layer * RR + tid];
    if (tid >= 32 && tid < 96) {
        lnw_s[tid - 32] = lnw[tid - 32];
        lnb_s[tid - 32] = lnb[tid - 32];
    }
    __syncthreads();

    int wid  = (blockIdx.x * 256 + tid) >> 5;            // node id
    int lane = tid & 31;
    int start = d_rowptr[wid], end = d_rowptr[wid + 1];
    int deg = end - start;
    float ad = d_adst[wid];
    float ax = 0.f, ay = 0.f;
    int c = lane * 2;

    if (deg <= 32) {
        // register-resident softmax
        int p = (lane < deg) ? d_adj[start + lane] : 0;
        int s = p & 0xFFFFF;
        float l = -1e30f;
        if (lane < deg) {
            l = d_asrc[s] + ad + rel_s[p >> 20];
            l = (l > 0.f) ? l : 0.2f * l;
        }
        float m = l;
        for (int o = 16; o; o >>= 1) m = fmaxf(m, __shfl_xor_sync(0xffffffffu, m, o));
        float ex = (lane < deg) ? expf(l - m) : 0.f;
        float den = ex;
        for (int o = 16; o; o >>= 1) den += __shfl_xor_sync(0xffffffffu, den, o);
        float coef_mine = ex / (den + 1e-16f);
#pragma unroll 4
        for (int i = 0; i < deg; i++) {
            float coef = __shfl_sync(0xffffffffu, coef_mine, i);
            int   si   = __shfl_sync(0xffffffffu, s, i);
            __half2 v = d_hph[si * 32 + lane];
            float2 f = __half22float2(v);
            ax += coef * f.x;
            ay += coef * f.y;
        }
    } else {
        // fallback: 3-pass via scratch
        float m = -1e30f;
        for (int i = start + lane; i < end; i += 32) {
            int p = d_adj[i];
            float l = d_asrc[p & 0xFFFFF] + ad + rel_s[p >> 20];
            l = (l > 0.f) ? l : 0.2f * l;
            d_escratch[i] = l;
            m = fmaxf(m, l);
        }
        for (int o = 16; o; o >>= 1) m = fmaxf(m, __shfl_xor_sync(0xffffffffu, m, o));
        __syncwarp();
        float den = 0.f;
        for (int i = start + lane; i < end; i += 32) {
            float ex = expf(d_escratch[i] - m);
            d_escratch[i] = ex;
            den += ex;
        }
        for (int o = 16; o; o >>= 1) den += __shfl_xor_sync(0xffffffffu, den, o);
        __syncwarp();
        float inv = 1.f / (den + 1e-16f);
        for (int i = start; i < end; i++) {
            int p = d_adj[i];
            float coef = d_escratch[i] * inv;
            __half2 v = d_hph[(p & 0xFFFFF) * 32 + lane];
            float2 f = __half22float2(v);
            ax += coef * f.x;
            ay += coef * f.y;
        }
    }

    float ox = ax + bias[c], oy = ay + bias[c + 1];
    if (use_skip) {
        const float* xl = buf(layer - 1);
        float pm = d_stats[(layer - 1) * 2], pi = d_stats[(layer - 1) * 2 + 1];
        float r0 = xl[wid * 64 + c], r1 = xl[wid * 64 + c + 1];
        ox += fmaxf((r0 - pm) * pi * lnw_s[c]     + lnb_s[c],     0.f);
        oy += fmaxf((r1 - pm) * pi * lnw_s[c + 1] + lnb_s[c + 1], 0.f);
    }
    float* hout = buf(layer);
    *(float2*)&hout[wid * 64 + c] = make_float2(ox, oy);

    // fused LN partial reduction (block -> d_part)
    float s  = ox + oy;
    float ss = ox * ox + oy * oy;
    for (int o = 16; o; o >>= 1) {
        s  += __shfl_xor_sync(0xffffffffu, s, o);
        ss += __shfl_xor_sync(0xffffffffu, ss, o);
    }
    int w = tid >> 5;
    if (lane == 0) { red[w][0] = s; red[w][1] = ss; }
    __syncthreads();
    if (tid == 0) {
        float ts = 0.f, tss = 0.f;
#pragma unroll
        for (int k = 0; k < 8; k++) { ts += red[k][0]; tss += red[k][1]; }
        d_part[blockIdx.x * 2]     = ts;
        d_part[blockIdx.x * 2 + 1] = tss;
    }
}

// ---------------- LN finisher: combine 12500 partials ----------------
__global__ void k_lnfin(int layer) {
    int tid = threadIdx.x;                               // 1024 threads
    float s = 0.f, ss = 0.f;
    for (int i = tid; i < NAGG_BLK; i += 1024) {
        s  += d_part[2 * i];
        ss += d_part[2 * i + 1];
    }
    for (int o = 16; o; o >>= 1) {
        s  += __shfl_xor_sync(0xffffffffu, s, o);
        ss += __shfl_xor_sync(0xffffffffu, ss, o);
    }
    __shared__ float sh[32][2];
    int w = tid >> 5, lane = tid & 31;
    if (lane == 0) { sh[w][0] = s; sh[w][1] = ss; }
    __syncthreads();
    if (w == 0) {
        s  = sh[lane][0];
        ss = sh[lane][1];
        for (int o = 16; o; o >>= 1) {
            s  += __shfl_xor_sync(0xffffffffu, s, o);
            ss += __shfl_xor_sync(0xffffffffu, ss, o);
        }
        if (lane == 0) {
            const float M = (float)NN * (float)CC;
            float mu  = s / M;
            float var = ss / M - mu * mu;
            var = var > 0.f ? var : 0.f;
            d_stats[layer * 2]     = mu;
            d_stats[layer * 2 + 1] = 1.f / (sqrtf(var) + 1e-5f);
        }
    }
}

// ---------------- output MLP (norm fused on load) + sigmoid ----------------
__global__ __launch_bounds__(256) void k_mlp(const float* __restrict__ w1,
        const float* __restrict__ b1, const float* __restrict__ w2,
        const float* __restrict__ b2,
        const float* __restrict__ lnw, const float* __restrict__ lnb,
        float* __restrict__ out) {
    __shared__ float w1t[100 * 64];                      // transposed [j][k]
    __shared__ float b1s[100];
    __shared__ float w2s[100];
    __shared__ float lnw_s[64], lnb_s[64];
    int tid = threadIdx.x;
    for (int i = tid; i < 6400; i += 256) {
        int k = i / 100, j = i % 100;
        w1t[j * 64 + k] = w1[i];
    }
    if (tid < 100) { b1s[tid] = b1[tid]; w2s[tid] = w2[tid]; }
    if (tid >= 128 && tid < 192) {
        lnw_s[tid - 128] = lnw[tid - 128];
        lnb_s[tid - 128] = lnb[tid - 128];
    }
    __syncthreads();
    int n = blockIdx.x * 256 + tid;
    if (n >= NN) return;
    float mu = d_stats[4], inv = d_stats[5];
    float hr[64];
#pragma unroll
    for (int k = 0; k < 64; k++) {
        float raw = d_b2[n * 64 + k];
        hr[k] = fmaxf((raw - mu) * inv * lnw_s[k] + lnb_s[k], 0.f);
    }
    float z = 0.f;
    for (int j = 0; j < 100; j += 2) {
        float a0 = b1s[j], a1 = b1s[j + 1];
#pragma unroll
        for (int k = 0; k < 64; k += 4) {
            float4 wa = *(const float4*)&w1t[j * 64 + k];
            float4 wb = *(const float4*)&w1t[(j + 1) * 64 + k];
            a0 += hr[k] * wa.x + hr[k + 1] * wa.y + hr[k + 2] * wa.z + hr[k + 3] * wa.w;
            a1 += hr[k] * wb.x + hr[k + 1] * wb.y + hr[k + 2] * wb.z + hr[k + 3] * wb.w;
        }
        z += fmaxf(a0, 0.f) * w2s[j] + fmaxf(a1, 0.f) * w2s[j + 1];
    }
    z += b2[0];
    out[n] = 1.f / (1.f + expf(-z));
}

// ---------------- launch ----------------
extern "C" void kernel_launch(void* const* d_in, const int* in_sizes, int n_in,
                              void* d_out, int out_size) {
    const float* x         = (const float*)d_in[0];
    const int*   ei        = (const int*)  d_in[1];
    const int*   et        = (const int*)  d_in[2];
    const float* W         = (const float*)d_in[3];
    const float* att_src   = (const float*)d_in[4];
    const float* att_dst   = (const float*)d_in[5];
    const float* lin_edge  = (const float*)d_in[6];
    const float* att_edge  = (const float*)d_in[7];
    const float* conv_bias = (const float*)d_in[8];
    const float* edge_emb  = (const float*)d_in[9];
    const float* ln_w      = (const float*)d_in[10];
    const float* ln_b      = (const float*)d_in[11];
    const float* w1        = (const float*)d_in[12];
    const float* b1        = (const float*)d_in[13];
    const float* w2        = (const float*)d_in[14];
    const float* b2        = (const float*)d_in[15];
    float* out = (float*)d_out;

    // CSR build (edges identical across layers -> once per call)
    k_zero<<<(NN + 255) / 256, 256>>>();
    k_deg<<<EE / 256, 256>>>(ei);
    k_scan1<<<NB_SCAN, 1024>>>();
    k_scan2<<<1, 128>>>();
    k_scan3<<<NB_SCAN, 1024>>>();
    k_fill<<<EE / 256, 256>>>(ei, et);
    k_relprep<<<LL * RR + 1, 64>>>(lin_edge, att_edge, edge_emb, W, att_src, att_dst);
    k_l0<<<NN * 32 / 256, 256>>>(x);

    for (int l = 0; l < LL; l++) {
        if (l > 0)
            k_gemm_alpha<<<NN / 32, 256>>>(l, W + l * CC * CC,
                                           att_src + l * CC, att_dst + l * CC,
                                           ln_w, ln_b);
        k_agg<<<NAGG_BLK, 256>>>(l, conv_bias + l * CC, ln_w, ln_b, l > 0 ? 1 : 0);
        k_lnfin<<<1, 1024>>>(l);
    }
    k_mlp<<<(NN + 255) / 256, 256>>>(w1, b1, w2, b2, ln_w, ln_b, out);
}

// round 8
// speedup vs baseline: 1.1314x; 1.0071x over previous
#include <cuda_runtime.h>
#include <cuda_fp16.h>
#include <math.h>

#define NN 100000
#define EE 1600000
#define CC 64
#define RR 20
#define LL 3
#define NB_SCAN 98        // ceil(100000/1024)
#define NAGG_BLK 12500    // NN/8
#define FULL 0xffffffffu

// ---------------- scratch (static device globals; no allocation) ----------------
__device__ float  d_b0[NN * CC];
__device__ float  d_b1[NN * CC];
__device__ float  d_b2[NN * CC];
__device__ __half2 d_hph[NN * 32];   // hp in fp16, row = 32 half2 = 64 ch
__device__ float  d_asrc[NN];
__device__ float  d_adst[NN];
__device__ float  d_escratch[EE];
__device__ int    d_deg[NN];
__device__ int    d_cursor[NN];
__device__ int    d_rowptr[NN + 1];
__device__ int    d_adj[EE];
__device__ int    d_bsum[128];
__device__ float  d_part[NAGG_BLK * 2];
__device__ float  d_relatt[LL * RR];
__device__ float  d_stats[LL * 2];   // per layer: mu, 1/(std+eps)
__device__ float  d_colsum[CC];      // layer-0: column sums of W0
__device__ float  d_l0s[2];          // layer-0: colsum·a_src, colsum·a_dst

__device__ __forceinline__ float* buf(int l) {
    return l == 0 ? d_b0 : (l == 1 ? d_b1 : d_b2);
}

// ---------------- CSR build ----------------
__global__ void k_zero() {
    int i = blockIdx.x * 256 + threadIdx.x;
    if (i < NN) { d_deg[i] = 0; d_cursor[i] = 0; }
}

__global__ void k_deg(const int* __restrict__ ei) {
    int e = blockIdx.x * 256 + threadIdx.x;
    if (e < EE) atomicAdd(&d_deg[ei[EE + e]], 1);
}

__global__ void k_scan1() {
    __shared__ int tmp[1024];
    int i = blockIdx.x * 1024 + threadIdx.x;
    int v = (i < NN) ? d_deg[i] : 0;
    tmp[threadIdx.x] = v;
    __syncthreads();
    for (int off = 1; off < 1024; off <<= 1) {
        int t = (threadIdx.x >= off) ? tmp[threadIdx.x - off] : 0;
        __syncthreads();
        tmp[threadIdx.x] += t;
        __syncthreads();
    }
    if (i < NN) d_rowptr[i] = tmp[threadIdx.x] - v;      // exclusive
    if (threadIdx.x == 1023) d_bsum[blockIdx.x] = tmp[1023];
}

__global__ void k_scan2() {
    int tid = threadIdx.x;
    int v = (tid < NB_SCAN) ? d_bsum[tid] : 0;
    int orig = v;
    int lane = tid & 31, w = tid >> 5;
    for (int o = 1; o < 32; o <<= 1) {
        int t = __shfl_up_sync(FULL, v, o);
        if (lane >= o) v += t;
    }
    __shared__ int ws[4];
    if (lane == 31) ws[w] = v;
    __syncthreads();
    for (int k = 0; k < w; k++) v += ws[k];
    if (tid < NB_SCAN) d_bsum[tid] = v - orig;           // exclusive block offsets
}

__global__ void k_scan3() {
    int i = blockIdx.x * 1024 + threadIdx.x;
    if (i < NN) d_rowptr[i] += d_bsum[blockIdx.x];
    if (i == 0) d_rowptr[NN] = EE;
}

__global__ void k_fill(const int* __restrict__ ei, const int* __restrict__ et) {
    int e = blockIdx.x * 256 + threadIdx.x;
    if (e < EE) {
        int s = ei[e];
        int d = ei[EE + e];
        int t = et[e];
        int pos = d_rowptr[d] + atomicAdd(&d_cursor[d], 1);
        d_adj[pos] = s | (t << 20);                      // src<2^20, type<32
    }
}

// ---------------- relation-attention scalars + layer-0 prep ----------------
__global__ void k_relprep(const float* __restrict__ lin_edge,
                          const float* __restrict__ att_edge,
                          const float* __restrict__ edge_emb,
                          const float* __restrict__ W,
                          const float* __restrict__ att_src,
                          const float* __restrict__ att_dst) {
    int j = threadIdx.x;                                 // 64 threads
    if (blockIdx.x < LL * RR) {
        int l = blockIdx.x / RR, r = blockIdx.x % RR;
        const float* We  = lin_edge + l * 8 * CC;
        const float* emb = edge_emb + (l * RR + r) * 8;
        float t = 0.f;
#pragma unroll
        for (int d = 0; d < 8; d++) t += emb[d] * We[d * CC + j];
        t *= att_edge[l * CC + j];
        for (int o = 16; o; o >>= 1) t += __shfl_xor_sync(FULL, t, o);
        __shared__ float rs[2];
        if ((j & 31) == 0) rs[j >> 5] = t;
        __syncthreads();
        if (j == 0) d_relatt[l * RR + r] = rs[0] + rs[1];
    } else {
        // layer-0 prep: colsum_j = sum_k W0[k][j]; scalars = colsum·a_{s,d}
        float cs = 0.f;
#pragma unroll
        for (int k = 0; k < CC; k++) cs += W[k * CC + j];
        d_colsum[j] = cs;
        float s1 = cs * att_src[j];
        float s2 = cs * att_dst[j];
        for (int o = 16; o; o >>= 1) {
            s1 += __shfl_xor_sync(FULL, s1, o);
            s2 += __shfl_xor_sync(FULL, s2, o);
        }
        __shared__ float r1[2], r2[2];
        if ((j & 31) == 0) { r1[j >> 5] = s1; r2[j >> 5] = s2; }
        __syncthreads();
        if (j == 0) { d_l0s[0] = r1[0] + r1[1]; d_l0s[1] = r2[0] + r2[1]; }
    }
}

// ---------------- layer-0 "gemm": hp = outer(x, colsum) ----------------
__global__ void k_l0(const float* __restrict__ x) {
    int i = blockIdx.x * 256 + threadIdx.x;              // half2 slot over NN*32
    int n = i >> 5, c2 = i & 31;
    float v = x[n];
    d_hph[i] = __floats2half2_rn(v * d_colsum[c2 * 2], v * d_colsum[c2 * 2 + 1]);
    if (i < NN) {
        float xv = x[i];
        d_asrc[i] = xv * d_l0s[0];
        d_adst[i] = xv * d_l0s[1];
    }
}

// ---- hp = norm(h) @ W (fp16 out) ; alpha_src/dst = hp @ a_{s,d} (layers 1,2) ----
__global__ __launch_bounds__(256) void k_gemm_alpha(int layer,
        const float* __restrict__ Wl,
        const float* __restrict__ as_g,
        const float* __restrict__ ad_g,
        const float* __restrict__ lnw,
        const float* __restrict__ lnb) {
    __shared__ float Ws[64 * 64];
    __shared__ float hs[32 * 65];
    __shared__ float lnw_s[64], lnb_s[64];
    const float* hin = buf(layer - 1);
    float mu  = d_stats[(layer - 1) * 2];
    float inv = d_stats[(layer - 1) * 2 + 1];
    int tid = threadIdx.x;
    if (tid < 64) { lnw_s[tid] = lnw[tid]; lnb_s[tid] = lnb[tid]; }
    const float4* W4 = (const float4*)Wl;
#pragma unroll
    for (int i = tid; i < 1024; i += 256) ((float4*)Ws)[i] = W4[i];
    __syncthreads();
    int base = blockIdx.x * 32;
#pragma unroll
    for (int i = tid; i < 2048; i += 256) {
        int nl = i >> 6, k = i & 63;
        float raw = hin[base * 64 + i];
        hs[nl * 65 + k] = fmaxf((raw - mu) * inv * lnw_s[k] + lnb_s[k], 0.f);
    }
    __syncthreads();

    int g = tid & 15, slot = tid >> 4;
    int j = g * 4;
    float4 a0 = make_float4(0.f, 0.f, 0.f, 0.f);
    float4 a1 = a0;
#pragma unroll
    for (int k = 0; k < 64; k++) {
        float4 w = *(const float4*)&Ws[k * 64 + j];
        float h0 = hs[slot * 65 + k];
        float h1 = hs[(slot + 16) * 65 + k];
        a0.x += h0 * w.x; a0.y += h0 * w.y; a0.z += h0 * w.z; a0.w += h0 * w.w;
        a1.x += h1 * w.x; a1.y += h1 * w.y; a1.z += h1 * w.z; a1.w += h1 * w.w;
    }
    int n0 = base + slot, n1 = base + slot + 16;
    {
        __half2 p0 = __floats2half2_rn(a0.x, a0.y);
        __half2 p1 = __floats2half2_rn(a0.z, a0.w);
        *(uint2*)&d_hph[n0 * 32 + g * 2] = make_uint2(*(unsigned*)&p0, *(unsigned*)&p1);
        __half2 q0 = __floats2half2_rn(a1.x, a1.y);
        __half2 q1 = __floats2half2_rn(a1.z, a1.w);
        *(uint2*)&d_hph[n1 * 32 + g * 2] = make_uint2(*(unsigned*)&q0, *(unsigned*)&q1);
    }

    float4 as4 = *(const float4*)&as_g[j];
    float4 ad4 = *(const float4*)&ad_g[j];
    float ps0 = a0.x * as4.x + a0.y * as4.y + a0.z * as4.z + a0.w * as4.w;
    float pd0 = a0.x * ad4.x + a0.y * ad4.y + a0.z * ad4.z + a0.w * ad4.w;
    float ps1 = a1.x * as4.x + a1.y * as4.y + a1.z * as4.z + a1.w * as4.w;
    float pd1 = a1.x * ad4.x + a1.y * ad4.y + a1.z * ad4.z + a1.w * ad4.w;
#pragma unroll
    for (int o = 8; o; o >>= 1) {
        ps0 += __shfl_down_sync(FULL, ps0, o, 16);
        pd0 += __shfl_down_sync(FULL, pd0, o, 16);
        ps1 += __shfl_down_sync(FULL, ps1, o, 16);
        pd1 += __shfl_down_sync(FULL, pd1, o, 16);
    }
    if (g == 0) {
        d_asrc[n0] = ps0; d_adst[n0] = pd0;
        d_asrc[n1] = ps1; d_adst[n1] = pd1;
    }
}

// ------- warp-per-dst GAT aggregation + fused LN partial reduction -------
__global__ __launch_bounds__(256) void k_agg(int layer, const float* __restrict__ bias,
                                             const float* __restrict__ lnw,
                                             const float* __restrict__ lnb,
                                             int use_skip) {
    __shared__ float rel_s[RR];
    __shared__ float lnw_s[64], lnb_s[64];
    __shared__ float red[8][2];
    int tid = threadIdx.x;
    if (tid < RR) rel_s[tid] = d_relatt[layer * RR + tid];
    if (tid >= 32 && tid < 96) {
        lnw_s[tid - 32] = lnw[tid - 32];
        lnb_s[tid - 32] = lnb[tid - 32];
    }
    __syncthreads();

    int wid  = (blockIdx.x * 256 + tid) >> 5;            // node id
    int lane = tid & 31;
    int start = d_rowptr[wid], end = d_rowptr[wid + 1];
    int deg = end - start;
    float ad = d_adst[wid];
    float ax = 0.f, ay = 0.f;
    int c = lane * 2;

    if (deg <= 32) {
        // register-resident softmax
        int p = (lane < deg) ? d_adj[start + lane] : 0;
        int s = p & 0xFFFFF;
        float l = -1e30f;
        if (lane < deg) {
            l = d_asrc[s] + ad + rel_s[p >> 20];
            l = (l > 0.f) ? l : 0.2f * l;
        }
        float m = l;
        for (int o = 16; o; o >>= 1) m = fmaxf(m, __shfl_xor_sync(FULL, m, o));
        float ex = (lane < deg) ? __expf(l - m) : 0.f;
        float den = ex;
        for (int o = 16; o; o >>= 1) den += __shfl_xor_sync(FULL, den, o);
        float coef_mine = ex / (den + 1e-16f);
#pragma unroll 4
        for (int i = 0; i < deg; i++) {
            float coef = __shfl_sync(FULL, coef_mine, i);
            int   si   = __shfl_sync(FULL, s, i);
            __half2 v = d_hph[si * 32 + lane];
            float2 f = __half22float2(v);
            ax += coef * f.x;
            ay += coef * f.y;
        }
    } else {
        // fallback: 3-pass via scratch
        float m = -1e30f;
        for (int i = start + lane; i < end; i += 32) {
            int p = d_adj[i];
            float l = d_asrc[p & 0xFFFFF] + ad + rel_s[p >> 20];
            l = (l > 0.f) ? l : 0.2f * l;
            d_escratch[i] = l;
            m = fmaxf(m, l);
        }
        for (int o = 16; o; o >>= 1) m = fmaxf(m, __shfl_xor_sync(FULL, m, o));
        __syncwarp();
        float den = 0.f;
        for (int i = start + lane; i < end; i += 32) {
            float ex = __expf(d_escratch[i] - m);
            d_escratch[i] = ex;
            den += ex;
        }
        for (int o = 16; o; o >>= 1) den += __shfl_xor_sync(FULL, den, o);
        __syncwarp();
        float inv = 1.f / (den + 1e-16f);
        for (int i = start; i < end; i++) {
            int p = d_adj[i];
            float coef = d_escratch[i] * inv;
            __half2 v = d_hph[(p & 0xFFFFF) * 32 + lane];
            float2 f = __half22float2(v);
            ax += coef * f.x;
            ay += coef * f.y;
        }
    }

    float ox = ax + bias[c], oy = ay + bias[c + 1];
    if (use_skip) {
        const float* xl = buf(layer - 1);
        float pm = d_stats[(layer - 1) * 2], pi = d_stats[(layer - 1) * 2 + 1];
        float r0 = xl[wid * 64 + c], r1 = xl[wid * 64 + c + 1];
        ox += fmaxf((r0 - pm) * pi * lnw_s[c]     + lnb_s[c],     0.f);
        oy += fmaxf((r1 - pm) * pi * lnw_s[c + 1] + lnb_s[c + 1], 0.f);
    }
    float* hout = buf(layer);
    *(float2*)&hout[wid * 64 + c] = make_float2(ox, oy);

    // fused LN partial reduction (block -> d_part)
    float s  = ox + oy;
    float ss = ox * ox + oy * oy;
    for (int o = 16; o; o >>= 1) {
        s  += __shfl_xor_sync(FULL, s, o);
        ss += __shfl_xor_sync(FULL, ss, o);
    }
    int w = tid >> 5;
    if (lane == 0) { red[w][0] = s; red[w][1] = ss; }
    __syncthreads();
    if (tid == 0) {
        float ts = 0.f, tss = 0.f;
#pragma unroll
        for (int k = 0; k < 8; k++) { ts += red[k][0]; tss += red[k][1]; }
        d_part[blockIdx.x * 2]     = ts;
        d_part[blockIdx.x * 2 + 1] = tss;
    }
}

// ---------------- LN finisher: combine 12500 partials ----------------
__global__ void k_lnfin(int layer) {
    int tid = threadIdx.x;                               // 1024 threads
    float s = 0.f, ss = 0.f;
    for (int i = tid; i < NAGG_BLK; i += 1024) {
        s  += d_part[2 * i];
        ss += d_part[2 * i + 1];
    }
    for (int o = 16; o; o >>= 1) {
        s  += __shfl_xor_sync(FULL, s, o);
        ss += __shfl_xor_sync(FULL, ss, o);
    }
    __shared__ float sh[32][2];
    int w = tid >> 5, lane = tid & 31;
    if (lane == 0) { sh[w][0] = s; sh[w][1] = ss; }
    __syncthreads();
    if (w == 0) {
        s  = sh[lane][0];
        ss = sh[lane][1];
        for (int o = 16; o; o >>= 1) {
            s  += __shfl_xor_sync(FULL, s, o);
            ss += __shfl_xor_sync(FULL, ss, o);
        }
        if (lane == 0) {
            const float M = (float)NN * (float)CC;
            float mu  = s / M;
            float var = ss / M - mu * mu;
            var = var > 0.f ? var : 0.f;
            d_stats[layer * 2]     = mu;
            d_stats[layer * 2 + 1] = 1.f / (sqrtf(var) + 1e-5f);
        }
    }
}

// ---------------- output MLP (norm fused on load) + sigmoid ----------------
__global__ __launch_bounds__(256) void k_mlp(const float* __restrict__ w1,
        const float* __restrict__ b1, const float* __restrict__ w2,
        const float* __restrict__ b2,
        const float* __restrict__ lnw, const float* __restrict__ lnb,
        float* __restrict__ out) {
    __shared__ float w1t[100 * 64];                      // transposed [j][k]
    __shared__ float b1s[100];
    __shared__ float w2s[100];
    __shared__ float lnw_s[64], lnb_s[64];
    int tid = threadIdx.x;
    for (int i = tid; i < 6400; i += 256) {
        int k = i / 100, j = i % 100;
        w1t[j * 64 + k] = w1[i];
    }
    if (tid < 100) { b1s[tid] = b1[tid]; w2s[tid] = w2[tid]; }
    if (tid >= 128 && tid < 192) {
        lnw_s[tid - 128] = lnw[tid - 128];
        lnb_s[tid - 128] = lnb[tid - 128];
    }
    __syncthreads();
    int n = blockIdx.x * 256 + tid;
    if (n >= NN) return;
    float mu = d_stats[4], inv = d_stats[5];
    float hr[64];
#pragma unroll
    for (int k = 0; k < 64; k++) {
        float raw = d_b2[n * 64 + k];
        hr[k] = fmaxf((raw - mu) * inv * lnw_s[k] + lnb_s[k], 0.f);
    }
    float z = 0.f;
    for (int j = 0; j < 100; j += 2) {
        float a0 = b1s[j], a1 = b1s[j + 1];
#pragma unroll
        for (int k = 0; k < 64; k += 4) {
            float4 wa = *(const float4*)&w1t[j * 64 + k];
            float4 wb = *(const float4*)&w1t[(j + 1) * 64 + k];
            a0 += hr[k] * wa.x + hr[k + 1] * wa.y + hr[k + 2] * wa.z + hr[k + 3] * wa.w;
            a1 += hr[k] * wb.x + hr[k + 1] * wb.y + hr[k + 2] * wb.z + hr[k + 3] * wb.w;
        }
        z += fmaxf(a0, 0.f) * w2s[j] + fmaxf(a1, 0.f) * w2s[j + 1];
    }
    z += b2[0];
    out[n] = 1.f / (1.f + __expf(-z));
}

// ---------------- launch ----------------
extern "C" void kernel_launch(void* const* d_in, const int* in_sizes, int n_in,
                              void* d_out, int out_size) {
    const float* x         = (const float*)d_in[0];
    const int*   ei        = (const int*)  d_in[1];
    const int*   et        = (const int*)  d_in[2];
    const float* W         = (const float*)d_in[3];
    const float* att_src   = (const float*)d_in[4];
    const float* att_dst   = (const float*)d_in[5];
    const float* lin_edge  = (const float*)d_in[6];
    const float* att_edge  = (const float*)d_in[7];
    const float* conv_bias = (const float*)d_in[8];
    const float* edge_emb  = (const float*)d_in[9];
    const float* ln_w      = (const float*)d_in[10];
    const float* ln_b      = (const float*)d_in[11];
    const float* w1        = (const float*)d_in[12];
    const float* b1        = (const float*)d_in[13];
    const float* w2        = (const float*)d_in[14];
    const float* b2        = (const float*)d_in[15];
    float* out = (float*)d_out;

    // CSR build (edges identical across layers -> once per call)
    k_zero<<<(NN + 255) / 256, 256>>>();
    k_deg<<<EE / 256, 256>>>(ei);
    k_scan1<<<NB_SCAN, 1024>>>();
    k_scan2<<<1, 128>>>();
    k_scan3<<<NB_SCAN, 1024>>>();
    k_fill<<<EE / 256, 256>>>(ei, et);
    k_relprep<<<LL * RR + 1, 64>>>(lin_edge, att_edge, edge_emb, W, att_src, att_dst);
    k_l0<<<NN * 32 / 256, 256>>>(x);

    for (int l = 0; l < LL; l++) {
        if (l > 0)
            k_gemm_alpha<<<NN / 32, 256>>>(l, W + l * CC * CC,
                                           att_src + l * CC, att_dst + l * CC,
                                           ln_w, ln_b);
        k_agg<<<NAGG_BLK, 256>>>(l, conv_bias + l * CC, ln_w, ln_b, l > 0 ? 1 : 0);
        k_lnfin<<<1, 1024>>>(l);
    }
    k_mlp<<<(NN + 255) / 256, 256>>>(w1, b1, w2, b2, ln_w, ln_b, out);
}

// round 9
// speedup vs baseline: 1.6354x; 1.4455x over previous
#include <cuda_runtime.h>
#include <cuda_fp16.h>
#include <math.h>

#define NN 100000
#define EE 1600000
#define CC 64
#define RR 20
#define LL 3
#define NB_SCAN 98        // ceil(100000/1024)
#define NAGG_BLK 12500    // NN/8
#define FULL 0xffffffffu

// ---------------- scratch (static device globals; no allocation) ----------------
__device__ float  d_b0[NN * CC];
__device__ float  d_b1[NN * CC];
__device__ float  d_b2[NN * CC];
__device__ __half2 d_hph[NN * 32];   // hp in fp16, row = 32 half2 = 64 ch
__device__ float  d_asrc[NN];
__device__ float  d_adst[NN];
__device__ float  d_escratch[EE];
__device__ int    d_deg[NN];
__device__ int    d_cursor[NN];
__device__ int    d_rowptr[NN + 1];
__device__ int    d_adj[EE];
__device__ int    d_bsum[128];
__device__ float  d_part[NAGG_BLK * 2];
__device__ float  d_relatt[LL * RR];
__device__ float  d_stats[LL * 2];   // per layer: mu, 1/(std+eps)
__device__ float  d_colsum[CC];      // layer-0: column sums of W0
__device__ float  d_l0s[2];          // layer-0: colsum·a_src, colsum·a_dst

__device__ __forceinline__ float* buf(int l) {
    return l == 0 ? d_b0 : (l == 1 ? d_b1 : d_b2);
}

// ---------------- CSR build ----------------
__global__ void k_zero() {
    int i = blockIdx.x * 256 + threadIdx.x;
    if (i < NN) { d_deg[i] = 0; d_cursor[i] = 0; }
}

__global__ void k_deg(const int* __restrict__ ei) {
    int e = blockIdx.x * 256 + threadIdx.x;
    if (e < EE) atomicAdd(&d_deg[ei[EE + e]], 1);
}

__global__ void k_scan1() {
    __shared__ int tmp[1024];
    int i = blockIdx.x * 1024 + threadIdx.x;
    int v = (i < NN) ? d_deg[i] : 0;
    tmp[threadIdx.x] = v;
    __syncthreads();
    for (int off = 1; off < 1024; off <<= 1) {
        int t = (threadIdx.x >= off) ? tmp[threadIdx.x - off] : 0;
        __syncthreads();
        tmp[threadIdx.x] += t;
        __syncthreads();
    }
    if (i < NN) d_rowptr[i] = tmp[threadIdx.x] - v;      // exclusive
    if (threadIdx.x == 1023) d_bsum[blockIdx.x] = tmp[1023];
}

__global__ void k_scan2() {
    int tid = threadIdx.x;
    int v = (tid < NB_SCAN) ? d_bsum[tid] : 0;
    int orig = v;
    int lane = tid & 31, w = tid >> 5;
    for (int o = 1; o < 32; o <<= 1) {
        int t = __shfl_up_sync(FULL, v, o);
        if (lane >= o) v += t;
    }
    __shared__ int ws[4];
    if (lane == 31) ws[w] = v;
    __syncthreads();
    for (int k = 0; k < w; k++) v += ws[k];
    if (tid < NB_SCAN) d_bsum[tid] = v - orig;           // exclusive block offsets
}

__global__ void k_scan3() {
    int i = blockIdx.x * 1024 + threadIdx.x;
    if (i < NN) d_rowptr[i] += d_bsum[blockIdx.x];
    if (i == 0) d_rowptr[NN] = EE;
}

__global__ void k_fill(const int* __restrict__ ei, const int* __restrict__ et) {
    int e = blockIdx.x * 256 + threadIdx.x;
    if (e < EE) {
        int s = ei[e];
        int d = ei[EE + e];
        int t = et[e];
        int pos = d_rowptr[d] + atomicAdd(&d_cursor[d], 1);
        d_adj[pos] = s | (t << 20);                      // src<2^20, type<32
    }
}

// ---------------- relation-attention scalars + layer-0 prep ----------------
__global__ void k_relprep(const float* __restrict__ lin_edge,
                          const float* __restrict__ att_edge,
                          const float* __restrict__ edge_emb,
                          const float* __restrict__ W,
                          const float* __restrict__ att_src,
                          const float* __restrict__ att_dst) {
    int j = threadIdx.x;                                 // 64 threads
    if (blockIdx.x < LL * RR) {
        int l = blockIdx.x / RR, r = blockIdx.x % RR;
        const float* We  = lin_edge + l * 8 * CC;
        const float* emb = edge_emb + (l * RR + r) * 8;
        float t = 0.f;
#pragma unroll
        for (int d = 0; d < 8; d++) t += emb[d] * We[d * CC + j];
        t *= att_edge[l * CC + j];
        for (int o = 16; o; o >>= 1) t += __shfl_xor_sync(FULL, t, o);
        __shared__ float rs[2];
        if ((j & 31) == 0) rs[j >> 5] = t;
        __syncthreads();
        if (j == 0) d_relatt[l * RR + r] = rs[0] + rs[1];
    } else {
        // layer-0 prep: colsum_j = sum_k W0[k][j]; scalars = colsum·a_{s,d}
        float cs = 0.f;
#pragma unroll
        for (int k = 0; k < CC; k++) cs += W[k * CC + j];
        d_colsum[j] = cs;
        float s1 = cs * att_src[j];
        float s2 = cs * att_dst[j];
        for (int o = 16; o; o >>= 1) {
            s1 += __shfl_xor_sync(FULL, s1, o);
            s2 += __shfl_xor_sync(FULL, s2, o);
        }
        __shared__ float r1[2], r2[2];
        if ((j & 31) == 0) { r1[j >> 5] = s1; r2[j >> 5] = s2; }
        __syncthreads();
        if (j == 0) { d_l0s[0] = r1[0] + r1[1]; d_l0s[1] = r2[0] + r2[1]; }
    }
}

// ---------------- layer-0 "gemm": hp = outer(x, colsum) ----------------
__global__ void k_l0(const float* __restrict__ x) {
    int i = blockIdx.x * 256 + threadIdx.x;              // half2 slot over NN*32
    int n = i >> 5, c2 = i & 31;
    float v = x[n];
    d_hph[i] = __floats2half2_rn(v * d_colsum[c2 * 2], v * d_colsum[c2 * 2 + 1]);
    if (i < NN) {
        float xv = x[i];
        d_asrc[i] = xv * d_l0s[0];
        d_adst[i] = xv * d_l0s[1];
    }
}

// ---------------- HMMA helper ----------------
__device__ __forceinline__ void mma16816(float& c0, float& c1, float& c2, float& c3,
        unsigned a0, unsigned a1, unsigned a2, unsigned a3,
        unsigned b0, unsigned b1) {
    asm volatile(
        "mma.sync.aligned.m16n8k16.row.col.f32.f16.f16.f32 "
        "{%0,%1,%2,%3}, {%4,%5,%6,%7}, {%8,%9}, {%0,%1,%2,%3};\n"
        : "+f"(c0), "+f"(c1), "+f"(c2), "+f"(c3)
        : "r"(a0), "r"(a1), "r"(a2), "r"(a3), "r"(b0), "r"(b1));
}

// ---- hp = relu(norm(h_prev)) @ W  (HMMA, fp16 out) + alpha vectors (layers 1,2) ----
__global__ __launch_bounds__(256) void k_gemm_alpha(int layer,
        const float* __restrict__ Wl,
        const float* __restrict__ as_g, const float* __restrict__ ad_g,
        const float* __restrict__ lnw,  const float* __restrict__ lnb) {
    __shared__ __half As[128 * 72];
    __shared__ __half Wt[64 * 72];
    __shared__ float as_s[64], ad_s[64], Ak[64], Bk[64];
    int tid = threadIdx.x;
    for (int i = tid; i < 4096; i += 256) {              // Wt[n][k] = W[k][n]
        int k = i >> 6, n = i & 63;
        Wt[n * 72 + k] = __float2half(Wl[i]);
    }
    if (tid < 64) { as_s[tid] = as_g[tid]; ad_s[tid] = ad_g[tid]; }
    float mu  = d_stats[(layer - 1) * 2];
    float inv = d_stats[(layer - 1) * 2 + 1];
    if (tid < 64) {
        float g = lnw[tid];
        Ak[tid] = inv * g;
        Bk[tid] = lnb[tid] - mu * inv * g;
    }
    __syncthreads();

    const float* hin = buf(layer - 1);
    int base = blockIdx.x * 128;
    for (int i = tid; i < 4096; i += 256) {              // fill A (half2)
        int node = i >> 5, k2 = (i & 31) * 2;
        int gn = base + node;
        float v0 = 0.f, v1 = 0.f;
        if (gn < NN) {
            float2 r = *(const float2*)&hin[gn * 64 + k2];
            v0 = fmaxf(Ak[k2] * r.x + Bk[k2], 0.f);
            v1 = fmaxf(Ak[k2 + 1] * r.y + Bk[k2 + 1], 0.f);
        }
        *(__half2*)&As[node * 72 + k2] = __floats2half2_rn(v0, v1);
    }
    __syncthreads();

    int w = tid >> 5, lane = tid & 31;
    int gid = lane >> 2, t = lane & 3;
    int r0 = (w * 16 + gid) * 72;
    unsigned af[16];
#pragma unroll
    for (int kk = 0; kk < 4; kk++) {
        int bk = kk * 16 + 2 * t;
        af[kk * 4 + 0] = *(const unsigned*)&As[r0 + bk];
        af[kk * 4 + 1] = *(const unsigned*)&As[r0 + 8 * 72 + bk];
        af[kk * 4 + 2] = *(const unsigned*)&As[r0 + bk + 8];
        af[kk * 4 + 3] = *(const unsigned*)&As[r0 + 8 * 72 + bk + 8];
    }
    int rowA = base + w * 16 + gid, rowB = rowA + 8;
    float psl = 0.f, pdl = 0.f, psh = 0.f, pdh = 0.f;
#pragma unroll
    for (int nt = 0; nt < 8; nt++) {
        float c0 = 0.f, c1 = 0.f, c2 = 0.f, c3 = 0.f;
        int wrow = (nt * 8 + gid) * 72;
#pragma unroll
        for (int kk = 0; kk < 4; kk++) {
            unsigned b0 = *(const unsigned*)&Wt[wrow + kk * 16 + 2 * t];
            unsigned b1 = *(const unsigned*)&Wt[wrow + kk * 16 + 2 * t + 8];
            mma16816(c0, c1, c2, c3, af[kk*4], af[kk*4+1], af[kk*4+2], af[kk*4+3], b0, b1);
        }
        int col = nt * 8 + 2 * t;
        if (rowA < NN) d_hph[rowA * 32 + nt * 4 + t] = __floats2half2_rn(c0, c1);
        if (rowB < NN) d_hph[rowB * 32 + nt * 4 + t] = __floats2half2_rn(c2, c3);
        psl += c0 * as_s[col] + c1 * as_s[col + 1];
        pdl += c0 * ad_s[col] + c1 * ad_s[col + 1];
        psh += c2 * as_s[col] + c3 * as_s[col + 1];
        pdh += c2 * ad_s[col] + c3 * ad_s[col + 1];
    }
#pragma unroll
    for (int o = 1; o <= 2; o <<= 1) {
        psl += __shfl_xor_sync(FULL, psl, o);
        pdl += __shfl_xor_sync(FULL, pdl, o);
        psh += __shfl_xor_sync(FULL, psh, o);
        pdh += __shfl_xor_sync(FULL, pdh, o);
    }
    if (t == 0) {
        if (rowA < NN) { d_asrc[rowA] = psl; d_adst[rowA] = pdl; }
        if (rowB < NN) { d_asrc[rowB] = psh; d_adst[rowB] = pdh; }
    }
}

// ------- warp-per-dst GAT aggregation + fused LN partial reduction -------
__global__ __launch_bounds__(256) void k_agg(int layer, const float* __restrict__ bias,
                                             const float* __restrict__ lnw,
                                             const float* __restrict__ lnb,
                                             int use_skip) {
    __shared__ float rel_s[RR];
    __shared__ float lnw_s[64], lnb_s[64];
    __shared__ float red[8][2];
    int tid = threadIdx.x;
    if (tid < RR) rel_s[tid] = d_relatt[layer * RR + tid];
    if (tid >= 32 && tid < 96) {
        lnw_s[tid - 32] = lnw[tid - 32];
        lnb_s[tid - 32] = lnb[tid - 32];
    }
    __syncthreads();

    int wid  = (blockIdx.x * 256 + tid) >> 5;            // node id
    int lane = tid & 31;
    int start = d_rowptr[wid], end = d_rowptr[wid + 1];
    int deg = end - start;
    float ad = d_adst[wid];
    float ax = 0.f, ay = 0.f;
    int c = lane * 2;

    if (deg <= 32) {
        // register-resident softmax
        int p = (lane < deg) ? d_adj[start + lane] : 0;
        int s = p & 0xFFFFF;
        float l = -1e30f;
        if (lane < deg) {
            l = d_asrc[s] + ad + rel_s[p >> 20];
            l = (l > 0.f) ? l : 0.2f * l;
        }
        float m = l;
        for (int o = 16; o; o >>= 1) m = fmaxf(m, __shfl_xor_sync(FULL, m, o));
        float ex = (lane < deg) ? __expf(l - m) : 0.f;
        float den = ex;
        for (int o = 16; o; o >>= 1) den += __shfl_xor_sync(FULL, den, o);
        float coef_mine = ex / (den + 1e-16f);
#pragma unroll 4
        for (int i = 0; i < deg; i++) {
            float coef = __shfl_sync(FULL, coef_mine, i);
            int   si   = __shfl_sync(FULL, s, i);
            __half2 v = d_hph[si * 32 + lane];
            float2 f = __half22float2(v);
            ax += coef * f.x;
            ay += coef * f.y;
        }
    } else {
        // fallback: 3-pass via scratch
        float m = -1e30f;
        for (int i = start + lane; i < end; i += 32) {
            int p = d_adj[i];
            float l = d_asrc[p & 0xFFFFF] + ad + rel_s[p >> 20];
            l = (l > 0.f) ? l : 0.2f * l;
            d_escratch[i] = l;
            m = fmaxf(m, l);
        }
        for (int o = 16; o; o >>= 1) m = fmaxf(m, __shfl_xor_sync(FULL, m, o));
        __syncwarp();
        float den = 0.f;
        for (int i = start + lane; i < end; i += 32) {
            float ex = __expf(d_escratch[i] - m);
            d_escratch[i] = ex;
            den += ex;
        }
        for (int o = 16; o; o >>= 1) den += __shfl_xor_sync(FULL, den, o);
        __syncwarp();
        float inv = 1.f / (den + 1e-16f);
        for (int i = start; i < end; i++) {
            int p = d_adj[i];
            float coef = d_escratch[i] * inv;
            __half2 v = d_hph[(p & 0xFFFFF) * 32 + lane];
            float2 f = __half22float2(v);
            ax += coef * f.x;
            ay += coef * f.y;
        }
    }

    float ox = ax + bias[c], oy = ay + bias[c + 1];
    if (use_skip) {
        const float* xl = buf(layer - 1);
        float pm = d_stats[(layer - 1) * 2], pi = d_stats[(layer - 1) * 2 + 1];
        float r0 = xl[wid * 64 + c], r1 = xl[wid * 64 + c + 1];
        ox += fmaxf((r0 - pm) * pi * lnw_s[c]     + lnb_s[c],     0.f);
        oy += fmaxf((r1 - pm) * pi * lnw_s[c + 1] + lnb_s[c + 1], 0.f);
    }
    float* hout = buf(layer);
    *(float2*)&hout[wid * 64 + c] = make_float2(ox, oy);

    // fused LN partial reduction (block -> d_part)
    float s  = ox + oy;
    float ss = ox * ox + oy * oy;
    for (int o = 16; o; o >>= 1) {
        s  += __shfl_xor_sync(FULL, s, o);
        ss += __shfl_xor_sync(FULL, ss, o);
    }
    int w = tid >> 5;
    if (lane == 0) { red[w][0] = s; red[w][1] = ss; }
    __syncthreads();
    if (tid == 0) {
        float ts = 0.f, tss = 0.f;
#pragma unroll
        for (int k = 0; k < 8; k++) { ts += red[k][0]; tss += red[k][1]; }
        d_part[blockIdx.x * 2]     = ts;
        d_part[blockIdx.x * 2 + 1] = tss;
    }
}

// ---------------- LN finisher: combine 12500 partials ----------------
__global__ void k_lnfin(int layer) {
    int tid = threadIdx.x;                               // 1024 threads
    float s = 0.f, ss = 0.f;
    for (int i = tid; i < NAGG_BLK; i += 1024) {
        s  += d_part[2 * i];
        ss += d_part[2 * i + 1];
    }
    for (int o = 16; o; o >>= 1) {
        s  += __shfl_xor_sync(FULL, s, o);
        ss += __shfl_xor_sync(FULL, ss, o);
    }
    __shared__ float sh[32][2];
    int w = tid >> 5, lane = tid & 31;
    if (lane == 0) { sh[w][0] = s; sh[w][1] = ss; }
    __syncthreads();
    if (w == 0) {
        s  = sh[lane][0];
        ss = sh[lane][1];
        for (int o = 16; o; o >>= 1) {
            s  += __shfl_xor_sync(FULL, s, o);
            ss += __shfl_xor_sync(FULL, ss, o);
        }
        if (lane == 0) {
            const float M = (float)NN * (float)CC;
            float mu  = s / M;
            float var = ss / M - mu * mu;
            var = var > 0.f ? var : 0.f;
            d_stats[layer * 2]     = mu;
            d_stats[layer * 2 + 1] = 1.f / (sqrtf(var) + 1e-5f);
        }
    }
}

// ---------------- MLP head via HMMA (norm fused on load) + sigmoid ----------------
__global__ __launch_bounds__(256) void k_mlp(const float* __restrict__ w1,
        const float* __restrict__ b1g, const float* __restrict__ w2,
        const float* __restrict__ b2,
        const float* __restrict__ lnw, const float* __restrict__ lnb,
        float* __restrict__ out) {
    __shared__ __half As[128 * 72];
    __shared__ __half Wt[104 * 72];
    __shared__ float b1s[104], w2s[104], Ak[64], Bk[64];
    int tid = threadIdx.x;
    for (int i = tid; i < 104 * 72; i += 256) Wt[i] = __float2half(0.f);
    if (tid < 104) {
        b1s[tid] = (tid < 100) ? b1g[tid] : 0.f;
        w2s[tid] = (tid < 100) ? w2[tid] : 0.f;
    }
    __syncthreads();
    for (int i = tid; i < 6400; i += 256) {              // Wt[n][k] = w1[k][n]
        int k = i / 100, n = i % 100;
        Wt[n * 72 + k] = __float2half(w1[i]);
    }
    float mu = d_stats[4], inv = d_stats[5];
    if (tid < 64) {
        float g = lnw[tid];
        Ak[tid] = inv * g;
        Bk[tid] = lnb[tid] - mu * inv * g;
    }
    __syncthreads();

    int base = blockIdx.x * 128;
    for (int i = tid; i < 4096; i += 256) {
        int node = i >> 5, k2 = (i & 31) * 2;
        int gn = base + node;
        float v0 = 0.f, v1 = 0.f;
        if (gn < NN) {
            float2 r = *(const float2*)&d_b2[gn * 64 + k2];
            v0 = fmaxf(Ak[k2] * r.x + Bk[k2], 0.f);
            v1 = fmaxf(Ak[k2 + 1] * r.y + Bk[k2 + 1], 0.f);
        }
        *(__half2*)&As[node * 72 + k2] = __floats2half2_rn(v0, v1);
    }
    __syncthreads();

    int w = tid >> 5, lane = tid & 31;
    int gid = lane >> 2, t = lane & 3;
    int r0 = (w * 16 + gid) * 72;
    unsigned af[16];
#pragma unroll
    for (int kk = 0; kk < 4; kk++) {
        int bk = kk * 16 + 2 * t;
        af[kk * 4 + 0] = *(const unsigned*)&As[r0 + bk];
        af[kk * 4 + 1] = *(const unsigned*)&As[r0 + 8 * 72 + bk];
        af[kk * 4 + 2] = *(const unsigned*)&As[r0 + bk + 8];
        af[kk * 4 + 3] = *(const unsigned*)&As[r0 + 8 * 72 + bk + 8];
    }
    float zl = 0.f, zh = 0.f;
#pragma unroll
    for (int nt = 0; nt < 13; nt++) {
        float c0 = 0.f, c1 = 0.f, c2 = 0.f, c3 = 0.f;
        int wrow = (nt * 8 + gid) * 72;
#pragma unroll
        for (int kk = 0; kk < 4; kk++) {
            unsigned b0 = *(const unsigned*)&Wt[wrow + kk * 16 + 2 * t];
            unsigned b1 = *(const unsigned*)&Wt[wrow + kk * 16 + 2 * t + 8];
            mma16816(c0, c1, c2, c3, af[kk*4], af[kk*4+1], af[kk*4+2], af[kk*4+3], b0, b1);
        }
        int col = nt * 8 + 2 * t;
        zl += fmaxf(c0 + b1s[col], 0.f) * w2s[col] + fmaxf(c1 + b1s[col + 1], 0.f) * w2s[col + 1];
        zh += fmaxf(c2 + b1s[col], 0.f) * w2s[col] + fmaxf(c3 + b1s[col + 1], 0.f) * w2s[col + 1];
    }
#pragma unroll
    for (int o = 1; o <= 2; o <<= 1) {
        zl += __shfl_xor_sync(FULL, zl, o);
        zh += __shfl_xor_sync(FULL, zh, o);
    }
    if (t == 0) {
        float bb = b2[0];
        int rowA = base + w * 16 + gid, rowB = rowA + 8;
        if (rowA < NN) out[rowA] = 1.f / (1.f + __expf(-(zl + bb)));
        if (rowB < NN) out[rowB] = 1.f / (1.f + __expf(-(zh + bb)));
    }
}

// ---------------- launch ----------------
extern "C" void kernel_launch(void* const* d_in, const int* in_sizes, int n_in,
                              void* d_out, int out_size) {
    const float* x         = (const float*)d_in[0];
    const int*   ei        = (const int*)  d_in[1];
    const int*   et        = (const int*)  d_in[2];
    const float* W         = (const float*)d_in[3];
    const float* att_src   = (const float*)d_in[4];
    const float* att_dst   = (const float*)d_in[5];
    const float* lin_edge  = (const float*)d_in[6];
    const float* att_edge  = (const float*)d_in[7];
    const float* conv_bias = (const float*)d_in[8];
    const float* edge_emb  = (const float*)d_in[9];
    const float* ln_w      = (const float*)d_in[10];
    const float* ln_b      = (const float*)d_in[11];
    const float* w1        = (const float*)d_in[12];
    const float* b1        = (const float*)d_in[13];
    const float* w2        = (const float*)d_in[14];
    const float* b2        = (const float*)d_in[15];
    float* out = (float*)d_out;

    // CSR build (edges identical across layers -> once per call)
    k_zero<<<(NN + 255) / 256, 256>>>();
    k_deg<<<EE / 256, 256>>>(ei);
    k_scan1<<<NB_SCAN, 1024>>>();
    k_scan2<<<1, 128>>>();
    k_scan3<<<NB_SCAN, 1024>>>();
    k_fill<<<EE / 256, 256>>>(ei, et);
    k_relprep<<<LL * RR + 1, 64>>>(lin_edge, att_edge, edge_emb, W, att_src, att_dst);
    k_l0<<<NN * 32 / 256, 256>>>(x);

    for (int l = 0; l < LL; l++) {
        if (l > 0)
            k_gemm_alpha<<<(NN + 127) / 128, 256>>>(l, W + l * CC * CC,
                                                    att_src + l * CC, att_dst + l * CC,
                                                    ln_w, ln_b);
        k_agg<<<NAGG_BLK, 256>>>(l, conv_bias + l * CC, ln_w, ln_b, l > 0 ? 1 : 0);
        k_lnfin<<<1, 1024>>>(l);
    }
    k_mlp<<<(NN + 127) / 128, 256>>>(w1, b1, w2, b2, ln_w, ln_b, out);
}

// round 10
// speedup vs baseline: 1.8989x; 1.1611x over previous
#include <cuda_runtime.h>
#include <cuda_fp16.h>
#include <math.h>

#define NN 100000
#define EE 1600000
#define CC 64
#define RR 20
#define LL 3
#define NB_SCAN 98        // ceil(100000/1024)
#define NAGG_BLK 12500    // NN/8
#define FULL 0xffffffffu

// ---------------- scratch (static device globals; no allocation) ----------------
__device__ float  d_b0[NN * CC];
__device__ float  d_b1[NN * CC];
__device__ float  d_b2[NN * CC];
__device__ __half2 d_hph[NN * 32];   // hp in fp16 (layers 1,2), row = 32 half2
__device__ float  d_asrc[NN];
__device__ float  d_adst[NN];
__device__ float  d_escratch[EE];
__device__ int    d_deg[NN];
__device__ int    d_cursor[NN];
__device__ int    d_rowptr[NN + 1];
__device__ int    d_adj[EE];
__device__ int    d_bsum[128];
__device__ float  d_part[NAGG_BLK * 2];
__device__ float  d_relatt[LL * RR];
__device__ float  d_stats[LL * 2];   // per layer: mu, 1/(std+eps)
__device__ float  d_colsum[CC];      // layer-0: column sums of W0
__device__ float  d_l0s[2];          // layer-0: colsum·a_src, colsum·a_dst

__device__ __forceinline__ float* buf(int l) {
    return l == 0 ? d_b0 : (l == 1 ? d_b1 : d_b2);
}

// ---------------- CSR build ----------------
__global__ void k_zero() {
    int i = blockIdx.x * 256 + threadIdx.x;
    if (i < NN) { d_deg[i] = 0; d_cursor[i] = 0; }
}

__global__ void k_deg(const int* __restrict__ ei) {
    int e = blockIdx.x * 256 + threadIdx.x;
    if (e < EE) atomicAdd(&d_deg[ei[EE + e]], 1);
}

__global__ void k_scan1() {
    __shared__ int tmp[1024];
    int i = blockIdx.x * 1024 + threadIdx.x;
    int v = (i < NN) ? d_deg[i] : 0;
    tmp[threadIdx.x] = v;
    __syncthreads();
    for (int off = 1; off < 1024; off <<= 1) {
        int t = (threadIdx.x >= off) ? tmp[threadIdx.x - off] : 0;
        __syncthreads();
        tmp[threadIdx.x] += t;
        __syncthreads();
    }
    if (i < NN) d_rowptr[i] = tmp[threadIdx.x] - v;      // exclusive
    if (threadIdx.x == 1023) d_bsum[blockIdx.x] = tmp[1023];
}

__global__ void k_scan2() {
    int tid = threadIdx.x;
    int v = (tid < NB_SCAN) ? d_bsum[tid] : 0;
    int orig = v;
    int lane = tid & 31, w = tid >> 5;
    for (int o = 1; o < 32; o <<= 1) {
        int t = __shfl_up_sync(FULL, v, o);
        if (lane >= o) v += t;
    }
    __shared__ int ws[4];
    if (lane == 31) ws[w] = v;
    __syncthreads();
    for (int k = 0; k < w; k++) v += ws[k];
    if (tid < NB_SCAN) d_bsum[tid] = v - orig;           // exclusive block offsets
}

__global__ void k_scan3() {
    int i = blockIdx.x * 1024 + threadIdx.x;
    if (i < NN) d_rowptr[i] += d_bsum[blockIdx.x];
    if (i == 0) d_rowptr[NN] = EE;
}

__global__ void k_fill(const int* __restrict__ ei, const int* __restrict__ et) {
    int e = blockIdx.x * 256 + threadIdx.x;
    if (e < EE) {
        int s = ei[e];
        int d = ei[EE + e];
        int t = et[e];
        int pos = d_rowptr[d] + atomicAdd(&d_cursor[d], 1);
        d_adj[pos] = s | (t << 20);                      // src<2^20, type<32
    }
}

// ---------------- relation-attention scalars + layer-0 prep ----------------
__global__ void k_relprep(const float* __restrict__ lin_edge,
                          const float* __restrict__ att_edge,
                          const float* __restrict__ edge_emb,
                          const float* __restrict__ W,
                          const float* __restrict__ att_src,
                          const float* __restrict__ att_dst) {
    int j = threadIdx.x;                                 // 64 threads
    if (blockIdx.x < LL * RR) {
        int l = blockIdx.x / RR, r = blockIdx.x % RR;
        const float* We  = lin_edge + l * 8 * CC;
        const float* emb = edge_emb + (l * RR + r) * 8;
        float t = 0.f;
#pragma unroll
        for (int d = 0; d < 8; d++) t += emb[d] * We[d * CC + j];
        t *= att_edge[l * CC + j];
        for (int o = 16; o; o >>= 1) t += __shfl_xor_sync(FULL, t, o);
        __shared__ float rs[2];
        if ((j & 31) == 0) rs[j >> 5] = t;
        __syncthreads();
        if (j == 0) d_relatt[l * RR + r] = rs[0] + rs[1];
    } else {
        // layer-0 prep: colsum_j = sum_k W0[k][j]; scalars = colsum·a_{s,d}
        float cs = 0.f;
#pragma unroll
        for (int k = 0; k < CC; k++) cs += W[k * CC + j];
        d_colsum[j] = cs;
        float s1 = cs * att_src[j];
        float s2 = cs * att_dst[j];
        for (int o = 16; o; o >>= 1) {
            s1 += __shfl_xor_sync(FULL, s1, o);
            s2 += __shfl_xor_sync(FULL, s2, o);
        }
        __shared__ float r1[2], r2[2];
        if ((j & 31) == 0) { r1[j >> 5] = s1; r2[j >> 5] = s2; }
        __syncthreads();
        if (j == 0) { d_l0s[0] = r1[0] + r1[1]; d_l0s[1] = r2[0] + r2[1]; }
    }
}

// ---- layer-0 aggregation: scalar softmax-weighted x gather, materialize h0 ----
__global__ __launch_bounds__(256) void k_agg0(const float* __restrict__ x,
                                              const float* __restrict__ bias) {
    __shared__ float rel_s[RR];
    __shared__ float cs_s[64], bi_s[64];
    __shared__ float red[8][2];
    int tid = threadIdx.x;
    if (tid < 64)                 cs_s[tid] = d_colsum[tid];
    else if (tid < 128)           bi_s[tid - 64] = bias[tid - 64];
    else if (tid < 128 + RR)      rel_s[tid - 128] = d_relatt[tid - 128];
    __syncthreads();
    float s0 = d_l0s[0], s1 = d_l0s[1];

    int wid  = (blockIdx.x * 256 + tid) >> 5;            // node id
    int lane = tid & 31;
    int start = d_rowptr[wid], end = d_rowptr[wid + 1];
    int deg = end - start;
    float xd = x[wid];
    float acc;

    if (deg <= 32) {
        int p = (lane < deg) ? d_adj[start + lane] : 0;
        float xs = (lane < deg) ? x[p & 0xFFFFF] : 0.f;
        float l = -1e30f;
        if (lane < deg) {
            l = xs * s0 + xd * s1 + rel_s[p >> 20];
            l = (l > 0.f) ? l : 0.2f * l;
        }
        float m = l;
        for (int o = 16; o; o >>= 1) m = fmaxf(m, __shfl_xor_sync(FULL, m, o));
        float ex = (lane < deg) ? __expf(l - m) : 0.f;
        float den = ex;
        for (int o = 16; o; o >>= 1) den += __shfl_xor_sync(FULL, den, o);
        float t = ex * xs;
        for (int o = 16; o; o >>= 1) t += __shfl_xor_sync(FULL, t, o);
        acc = t / (den + 1e-16f);
    } else {
        float m = -1e30f;
        for (int i = start + lane; i < end; i += 32) {
            int p = d_adj[i];
            float l = x[p & 0xFFFFF] * s0 + xd * s1 + rel_s[p >> 20];
            l = (l > 0.f) ? l : 0.2f * l;
            d_escratch[i] = l;
            m = fmaxf(m, l);
        }
        for (int o = 16; o; o >>= 1) m = fmaxf(m, __shfl_xor_sync(FULL, m, o));
        __syncwarp();
        float den = 0.f, num = 0.f;
        for (int i = start + lane; i < end; i += 32) {
            int p = d_adj[i];
            float ex = __expf(d_escratch[i] - m);
            den += ex;
            num += ex * x[p & 0xFFFFF];
        }
        for (int o = 16; o; o >>= 1) {
            den += __shfl_xor_sync(FULL, den, o);
            num += __shfl_xor_sync(FULL, num, o);
        }
        acc = num / (den + 1e-16f);
    }

    // materialize h0 row: acc*colsum + bias  (exact fp32)
    int c = lane * 2;
    float ox = acc * cs_s[c]     + bi_s[c];
    float oy = acc * cs_s[c + 1] + bi_s[c + 1];
    *(float2*)&d_b0[wid * 64 + c] = make_float2(ox, oy);

    // fused LN partial reduction (block -> d_part)
    float s  = ox + oy;
    float ss = ox * ox + oy * oy;
    for (int o = 16; o; o >>= 1) {
        s  += __shfl_xor_sync(FULL, s, o);
        ss += __shfl_xor_sync(FULL, ss, o);
    }
    int w = tid >> 5;
    if (lane == 0) { red[w][0] = s; red[w][1] = ss; }
    __syncthreads();
    if (tid == 0) {
        float ts = 0.f, tss = 0.f;
#pragma unroll
        for (int k = 0; k < 8; k++) { ts += red[k][0]; tss += red[k][1]; }
        d_part[blockIdx.x * 2]     = ts;
        d_part[blockIdx.x * 2 + 1] = tss;
    }
}

// ---------------- HMMA helper ----------------
__device__ __forceinline__ void mma16816(float& c0, float& c1, float& c2, float& c3,
        unsigned a0, unsigned a1, unsigned a2, unsigned a3,
        unsigned b0, unsigned b1) {
    asm volatile(
        "mma.sync.aligned.m16n8k16.row.col.f32.f16.f16.f32 "
        "{%0,%1,%2,%3}, {%4,%5,%6,%7}, {%8,%9}, {%0,%1,%2,%3};\n"
        : "+f"(c0), "+f"(c1), "+f"(c2), "+f"(c3)
        : "r"(a0), "r"(a1), "r"(a2), "r"(a3), "r"(b0), "r"(b1));
}

// ---- hp = relu(norm(h_prev)) @ W  (HMMA, fp16 out) + alpha vectors (layers 1,2) ----
__global__ __launch_bounds__(256) void k_gemm_alpha(int layer,
        const float* __restrict__ Wl,
        const float* __restrict__ as_g, const float* __restrict__ ad_g,
        const float* __restrict__ lnw,  const float* __restrict__ lnb) {
    __shared__ __half As[128 * 72];
    __shared__ __half Wt[64 * 72];
    __shared__ float as_s[64], ad_s[64], Ak[64], Bk[64];
    int tid = threadIdx.x;
    for (int i = tid; i < 4096; i += 256) {              // Wt[n][k] = W[k][n]
        int k = i >> 6, n = i & 63;
        Wt[n * 72 + k] = __float2half(Wl[i]);
    }
    if (tid < 64) { as_s[tid] = as_g[tid]; ad_s[tid] = ad_g[tid]; }
    float mu  = d_stats[(layer - 1) * 2];
    float inv = d_stats[(layer - 1) * 2 + 1];
    if (tid < 64) {
        float g = lnw[tid];
        Ak[tid] = inv * g;
        Bk[tid] = lnb[tid] - mu * inv * g;
    }
    __syncthreads();

    const float* hin = buf(layer - 1);
    int base = blockIdx.x * 128;
    for (int i = tid; i < 4096; i += 256) {              // fill A (half2)
        int node = i >> 5, k2 = (i & 31) * 2;
        int gn = base + node;
        float v0 = 0.f, v1 = 0.f;
        if (gn < NN) {
            float2 r = *(const float2*)&hin[gn * 64 + k2];
            v0 = fmaxf(Ak[k2] * r.x + Bk[k2], 0.f);
            v1 = fmaxf(Ak[k2 + 1] * r.y + Bk[k2 + 1], 0.f);
        }
        *(__half2*)&As[node * 72 + k2] = __floats2half2_rn(v0, v1);
    }
    __syncthreads();

    int w = tid >> 5, lane = tid & 31;
    int gid = lane >> 2, t = lane & 3;
    int r0 = (w * 16 + gid) * 72;
    unsigned af[16];
#pragma unroll
    for (int kk = 0; kk < 4; kk++) {
        int bk = kk * 16 + 2 * t;
        af[kk * 4 + 0] = *(const unsigned*)&As[r0 + bk];
        af[kk * 4 + 1] = *(const unsigned*)&As[r0 + 8 * 72 + bk];
        af[kk * 4 + 2] = *(const unsigned*)&As[r0 + bk + 8];
        af[kk * 4 + 3] = *(const unsigned*)&As[r0 + 8 * 72 + bk + 8];
    }
    int rowA = base + w * 16 + gid, rowB = rowA + 8;
    float psl = 0.f, pdl = 0.f, psh = 0.f, pdh = 0.f;
#pragma unroll
    for (int nt = 0; nt < 8; nt++) {
        float c0 = 0.f, c1 = 0.f, c2 = 0.f, c3 = 0.f;
        int wrow = (nt * 8 + gid) * 72;
#pragma unroll
        for (int kk = 0; kk < 4; kk++) {
            unsigned b0 = *(const unsigned*)&Wt[wrow + kk * 16 + 2 * t];
            unsigned b1 = *(const unsigned*)&Wt[wrow + kk * 16 + 2 * t + 8];
            mma16816(c0, c1, c2, c3, af[kk*4], af[kk*4+1], af[kk*4+2], af[kk*4+3], b0, b1);
        }
        int col = nt * 8 + 2 * t;
        if (rowA < NN) d_hph[rowA * 32 + nt * 4 + t] = __floats2half2_rn(c0, c1);
        if (rowB < NN) d_hph[rowB * 32 + nt * 4 + t] = __floats2half2_rn(c2, c3);
        psl += c0 * as_s[col] + c1 * as_s[col + 1];
        pdl += c0 * ad_s[col] + c1 * ad_s[col + 1];
        psh += c2 * as_s[col] + c3 * as_s[col + 1];
        pdh += c2 * ad_s[col] + c3 * ad_s[col + 1];
    }
#pragma unroll
    for (int o = 1; o <= 2; o <<= 1) {
        psl += __shfl_xor_sync(FULL, psl, o);
        pdl += __shfl_xor_sync(FULL, pdl, o);
        psh += __shfl_xor_sync(FULL, psh, o);
        pdh += __shfl_xor_sync(FULL, pdh, o);
    }
    if (t == 0) {
        if (rowA < NN) { d_asrc[rowA] = psl; d_adst[rowA] = pdl; }
        if (rowB < NN) { d_asrc[rowB] = psh; d_adst[rowB] = pdh; }
    }
}

// ------- warp-per-dst GAT aggregation (pair-gather) + fused LN partials -------
__global__ __launch_bounds__(256) void k_agg(int layer, const float* __restrict__ bias,
                                             const float* __restrict__ lnw,
                                             const float* __restrict__ lnb) {
    __shared__ float rel_s[RR];
    __shared__ float lnw_s[64], lnb_s[64];
    __shared__ float red[8][2];
    int tid = threadIdx.x;
    if (tid < RR) rel_s[tid] = d_relatt[layer * RR + tid];
    if (tid >= 32 && tid < 96) {
        lnw_s[tid - 32] = lnw[tid - 32];
        lnb_s[tid - 32] = lnb[tid - 32];
    }
    __syncthreads();

    int wid  = (blockIdx.x * 256 + tid) >> 5;            // node id
    int lane = tid & 31;
    int start = d_rowptr[wid], end = d_rowptr[wid + 1];
    int deg = end - start;
    float ad = d_adst[wid];
    float a0 = 0.f, a1 = 0.f, a2 = 0.f, a3 = 0.f;
    int q = lane & 15;                                   // lane q owns channels 4q..4q+3

    if (deg <= 32) {
        int p = (lane < deg) ? d_adj[start + lane] : 0;
        int s = p & 0xFFFFF;
        float l = -1e30f;
        if (lane < deg) {
            l = d_asrc[s] + ad + rel_s[p >> 20];
            l = (l > 0.f) ? l : 0.2f * l;
        }
        float m = l;
        for (int o = 16; o; o >>= 1) m = fmaxf(m, __shfl_xor_sync(FULL, m, o));
        float ex = (lane < deg) ? __expf(l - m) : 0.f;
        float den = ex;
        for (int o = 16; o; o >>= 1) den += __shfl_xor_sync(FULL, den, o);
        float coef_mine = ex / (den + 1e-16f);
        int hs = lane >> 4;
        int npair = (deg + 1) >> 1;
        for (int i = 0; i < npair; i++) {
            int idx = 2 * i + hs;
            float cf = __shfl_sync(FULL, coef_mine, idx);
            int   si = __shfl_sync(FULL, s, idx);
            uint2 v = *(const uint2*)&d_hph[si * 32 + q * 2];
            float2 f0 = __half22float2(*(__half2*)&v.x);
            float2 f1 = __half22float2(*(__half2*)&v.y);
            a0 += cf * f0.x; a1 += cf * f0.y;
            a2 += cf * f1.x; a3 += cf * f1.y;
        }
        a0 += __shfl_xor_sync(FULL, a0, 16);
        a1 += __shfl_xor_sync(FULL, a1, 16);
        a2 += __shfl_xor_sync(FULL, a2, 16);
        a3 += __shfl_xor_sync(FULL, a3, 16);
    } else {
        float m = -1e30f;
        for (int i = start + lane; i < end; i += 32) {
            int p = d_adj[i];
            float l = d_asrc[p & 0xFFFFF] + ad + rel_s[p >> 20];
            l = (l > 0.f) ? l : 0.2f * l;
            d_escratch[i] = l;
            m = fmaxf(m, l);
        }
        for (int o = 16; o; o >>= 1) m = fmaxf(m, __shfl_xor_sync(FULL, m, o));
        __syncwarp();
        float den = 0.f;
        for (int i = start + lane; i < end; i += 32) {
            float ex = __expf(d_escratch[i] - m);
            d_escratch[i] = ex;
            den += ex;
        }
        for (int o = 16; o; o >>= 1) den += __shfl_xor_sync(FULL, den, o);
        __syncwarp();
        float invd = 1.f / (den + 1e-16f);
        float ax = 0.f, ay = 0.f;                        // lane owns ch 2*lane, +1
        for (int i = start; i < end; i++) {
            int p = d_adj[i];
            float cf = d_escratch[i] * invd;
            float2 f = __half22float2(d_hph[(p & 0xFFFFF) * 32 + lane]);
            ax += cf * f.x;
            ay += cf * f.y;
        }
        a0 = __shfl_sync(FULL, ax, 2 * q);
        a1 = __shfl_sync(FULL, ay, 2 * q);
        a2 = __shfl_sync(FULL, ax, 2 * q + 1);
        a3 = __shfl_sync(FULL, ay, 2 * q + 1);
    }

    // epilogue: lanes 0-15 own channels 4q..4q+3; skip = relu(norm(prev))
    float o0 = 0.f, o1 = 0.f, o2 = 0.f, o3 = 0.f;
    if (lane < 16) {
        int c = q * 4;
        const float* xl = buf(layer - 1);
        float pm = d_stats[(layer - 1) * 2], pi = d_stats[(layer - 1) * 2 + 1];
        float4 r = *(const float4*)&xl[wid * 64 + c];
        float s0 = fmaxf((r.x - pm) * pi * lnw_s[c]     + lnb_s[c],     0.f);
        float s1 = fmaxf((r.y - pm) * pi * lnw_s[c + 1] + lnb_s[c + 1], 0.f);
        float s2 = fmaxf((r.z - pm) * pi * lnw_s[c + 2] + lnb_s[c + 2], 0.f);
        float s3 = fmaxf((r.w - pm) * pi * lnw_s[c + 3] + lnb_s[c + 3], 0.f);
        o0 = a0 + bias[c]     + s0;
        o1 = a1 + bias[c + 1] + s1;
        o2 = a2 + bias[c + 2] + s2;
        o3 = a3 + bias[c + 3] + s3;
        float* hout = buf(layer);
        *(float4*)&hout[wid * 64 + c] = make_float4(o0, o1, o2, o3);
    }

    // fused LN partial reduction (block -> d_part)
    float s  = o0 + o1 + o2 + o3;
    float ss = o0 * o0 + o1 * o1 + o2 * o2 + o3 * o3;
    for (int o = 16; o; o >>= 1) {
        s  += __shfl_xor_sync(FULL, s, o);
        ss += __shfl_xor_sync(FULL, ss, o);
    }
    int w = tid >> 5;
    if (lane == 0) { red[w][0] = s; red[w][1] = ss; }
    __syncthreads();
    if (tid == 0) {
        float ts = 0.f, tss = 0.f;
#pragma unroll
        for (int k = 0; k < 8; k++) { ts += red[k][0]; tss += red[k][1]; }
        d_part[blockIdx.x * 2]     = ts;
        d_part[blockIdx.x * 2 + 1] = tss;
    }
}

// ---------------- LN finisher: combine 12500 partials ----------------
__global__ void k_lnfin(int layer) {
    int tid = threadIdx.x;                               // 1024 threads
    float s = 0.f, ss = 0.f;
    for (int i = tid; i < NAGG_BLK; i += 1024) {
        s  += d_part[2 * i];
        ss += d_part[2 * i + 1];
    }
    for (int o = 16; o; o >>= 1) {
        s  += __shfl_xor_sync(FULL, s, o);
        ss += __shfl_xor_sync(FULL, ss, o);
    }
    __shared__ float sh[32][2];
    int w = tid >> 5, lane = tid & 31;
    if (lane == 0) { sh[w][0] = s; sh[w][1] = ss; }
    __syncthreads();
    if (w == 0) {
        s  = sh[lane][0];
        ss = sh[lane][1];
        for (int o = 16; o; o >>= 1) {
            s  += __shfl_xor_sync(FULL, s, o);
            ss += __shfl_xor_sync(FULL, ss, o);
        }
        if (lane == 0) {
            const float M = (float)NN * (float)CC;
            float mu  = s / M;
            float var = ss / M - mu * mu;
            var = var > 0.f ? var : 0.f;
            d_stats[layer * 2]     = mu;
            d_stats[layer * 2 + 1] = 1.f / (sqrtf(var) + 1e-5f);
        }
    }
}

// ---------------- MLP head via HMMA (norm fused on load) + sigmoid ----------------
__global__ __launch_bounds__(256) void k_mlp(const float* __restrict__ w1,
        const float* __restrict__ b1g, const float* __restrict__ w2,
        const float* __restrict__ b2,
        const float* __restrict__ lnw, const float* __restrict__ lnb,
        float* __restrict__ out) {
    __shared__ __half As[128 * 72];
    __shared__ __half Wt[104 * 72];
    __shared__ float b1s[104], w2s[104], Ak[64], Bk[64];
    int tid = threadIdx.x;
    for (int i = tid; i < 104 * 72; i += 256) Wt[i] = __float2half(0.f);
    if (tid < 104) {
        b1s[tid] = (tid < 100) ? b1g[tid] : 0.f;
        w2s[tid] = (tid < 100) ? w2[tid] : 0.f;
    }
    __syncthreads();
    for (int i = tid; i < 6400; i += 256) {              // Wt[n][k] = w1[k][n]
        int k = i / 100, n = i % 100;
        Wt[n * 72 + k] = __float2half(w1[i]);
    }
    float mu = d_stats[4], inv = d_stats[5];
    if (tid < 64) {
        float g = lnw[tid];
        Ak[tid] = inv * g;
        Bk[tid] = lnb[tid] - mu * inv * g;
    }
    __syncthreads();

    int base = blockIdx.x * 128;
    for (int i = tid; i < 4096; i += 256) {
        int node = i >> 5, k2 = (i & 31) * 2;
        int gn = base + node;
        float v0 = 0.f, v1 = 0.f;
        if (gn < NN) {
            float2 r = *(const float2*)&d_b2[gn * 64 + k2];
            v0 = fmaxf(Ak[k2] * r.x + Bk[k2], 0.f);
            v1 = fmaxf(Ak[k2 + 1] * r.y + Bk[k2 + 1], 0.f);
        }
        *(__half2*)&As[node * 72 + k2] = __floats2half2_rn(v0, v1);
    }
    __syncthreads();

    int w = tid >> 5, lane = tid & 31;
    int gid = lane >> 2, t = lane & 3;
    int r0 = (w * 16 + gid) * 72;
    unsigned af[16];
#pragma unroll
    for (int kk = 0; kk < 4; kk++) {
        int bk = kk * 16 + 2 * t;
        af[kk * 4 + 0] = *(const unsigned*)&As[r0 + bk];
        af[kk * 4 + 1] = *(const unsigned*)&As[r0 + 8 * 72 + bk];
        af[kk * 4 + 2] = *(const unsigned*)&As[r0 + bk + 8];
        af[kk * 4 + 3] = *(const unsigned*)&As[r0 + 8 * 72 + bk + 8];
    }
    float zl = 0.f, zh = 0.f;
#pragma unroll
    for (int nt = 0; nt < 13; nt++) {
        float c0 = 0.f, c1 = 0.f, c2 = 0.f, c3 = 0.f;
        int wrow = (nt * 8 + gid) * 72;
#pragma unroll
        for (int kk = 0; kk < 4; kk++) {
            unsigned b0 = *(const unsigned*)&Wt[wrow + kk * 16 + 2 * t];
            unsigned b1 = *(const unsigned*)&Wt[wrow + kk * 16 + 2 * t + 8];
            mma16816(c0, c1, c2, c3, af[kk*4], af[kk*4+1], af[kk*4+2], af[kk*4+3], b0, b1);
        }
        int col = nt * 8 + 2 * t;
        zl += fmaxf(c0 + b1s[col], 0.f) * w2s[col] + fmaxf(c1 + b1s[col + 1], 0.f) * w2s[col + 1];
        zh += fmaxf(c2 + b1s[col], 0.f) * w2s[col] + fmaxf(c3 + b1s[col + 1], 0.f) * w2s[col + 1];
    }
#pragma unroll
    for (int o = 1; o <= 2; o <<= 1) {
        zl += __shfl_xor_sync(FULL, zl, o);
        zh += __shfl_xor_sync(FULL, zh, o);
    }
    if (t == 0) {
        float bb = b2[0];
        int rowA = base + w * 16 + gid, rowB = rowA + 8;
        if (rowA < NN) out[rowA] = 1.f / (1.f + __expf(-(zl + bb)));
        if (rowB < NN) out[rowB] = 1.f / (1.f + __expf(-(zh + bb)));
    }
}

// ---------------- launch ----------------
extern "C" void kernel_launch(void* const* d_in, const int* in_sizes, int n_in,
                              void* d_out, int out_size) {
    const float* x         = (const float*)d_in[0];
    const int*   ei        = (const int*)  d_in[1];
    const int*   et        = (const int*)  d_in[2];
    const float* W         = (const float*)d_in[3];
    const float* att_src   = (const float*)d_in[4];
    const float* att_dst   = (const float*)d_in[5];
    const float* lin_edge  = (const float*)d_in[6];
    const float* att_edge  = (const float*)d_in[7];
    const float* conv_bias = (const float*)d_in[8];
    const float* edge_emb  = (const float*)d_in[9];
    const float* ln_w      = (const float*)d_in[10];
    const float* ln_b      = (const float*)d_in[11];
    const float* w1        = (const float*)d_in[12];
    const float* b1        = (const float*)d_in[13];
    const float* w2        = (const float*)d_in[14];
    const float* b2        = (const float*)d_in[15];
    float* out = (float*)d_out;

    // CSR build (edges identical across layers -> once per call)
    k_zero<<<(NN + 255) / 256, 256>>>();
    k_deg<<<EE / 256, 256>>>(ei);
    k_scan1<<<NB_SCAN, 1024>>>();
    k_scan2<<<1, 128>>>();
    k_scan3<<<NB_SCAN, 1024>>>();
    k_fill<<<EE / 256, 256>>>(ei, et);
    k_relprep<<<LL * RR + 1, 64>>>(lin_edge, att_edge, edge_emb, W, att_src, att_dst);

    k_agg0<<<NAGG_BLK, 256>>>(x, conv_bias);
    k_lnfin<<<1, 1024>>>(0);
    for (int l = 1; l < LL; l++) {
        k_gemm_alpha<<<(NN + 127) / 128, 256>>>(l, W + l * CC * CC,
                                                att_src + l * CC, att_dst + l * CC,
                                                ln_w, ln_b);
        k_agg<<<NAGG_BLK, 256>>>(l, conv_bias + l * CC, ln_w, ln_b);
        k_lnfin<<<1, 1024>>>(l);
    }
    k_mlp<<<(NN + 127) / 128, 256>>>(w1, b1, w2, b2, ln_w, ln_b, out);
}

// round 11
// speedup vs baseline: 1.9659x; 1.0353x over previous
#include <cuda_runtime.h>
#include <cuda_fp16.h>
#include <math.h>

#define NN 100000
#define EE 1600000
#define CC 64
#define RR 20
#define LL 3
#define NB_SCAN 98        // ceil(100000/1024)
#define NAGG_BLK 12500    // NN/8
#define DEG_BLOCKS 6250   // EE/256
#define FULL 0xffffffffu

// ---------------- scratch (static device globals; zero-initialized at load) ----------------
__device__ float  d_b0[NN * CC];
__device__ float  d_b1[NN * CC];
__device__ float  d_b2[NN * CC];
__device__ __half2 d_hph[NN * 32];   // hp in fp16 (layers 1,2), row = 32 half2
__device__ __half d_asrch[NN];       // alpha_src in fp16 (fits L1)
__device__ float  d_adst[NN];
__device__ float  d_escratch[EE];
__device__ int    d_deg[NN];         // self-cleaning: zeroed by k_scan1 after read
__device__ int    d_cursor[NN];      // self-cleaning: zeroed by k_scan3 before k_fill
__device__ int    d_rowptr[NN + 1];
__device__ int    d_adj[EE];
__device__ int    d_bsum[128];
__device__ float  d_part[NAGG_BLK * 2];
__device__ float  d_relatt[LL * RR];
__device__ float  d_stats[LL * 2];   // per layer: mu, 1/(std+eps)
__device__ float  d_colsum[CC];      // layer-0: column sums of W0
__device__ float  d_l0s[2];          // layer-0: colsum·a_src, colsum·a_dst

__device__ __forceinline__ float* buf(int l) {
    return l == 0 ? d_b0 : (l == 1 ? d_b1 : d_b2);
}

// ------- merged: degree histogram (blocks 0..6249) + relprep (blocks 6250..6310) -------
__global__ void k_degrel(const int* __restrict__ ei,
                         const float* __restrict__ lin_edge,
                         const float* __restrict__ att_edge,
                         const float* __restrict__ edge_emb,
                         const float* __restrict__ W,
                         const float* __restrict__ att_src,
                         const float* __restrict__ att_dst) {
    int b = blockIdx.x;
    int tid = threadIdx.x;
    if (b < DEG_BLOCKS) {
        int e = b * 256 + tid;
        if (e < EE) atomicAdd(&d_deg[ei[EE + e]], 1);
        return;
    }
    int bb = b - DEG_BLOCKS;
    int j = tid;                                         // only j<64 active
    if (bb < LL * RR) {
        int l = bb / RR, r = bb % RR;
        float t = 0.f;
        if (j < 64) {
            const float* We  = lin_edge + l * 8 * CC;
            const float* emb = edge_emb + (l * RR + r) * 8;
#pragma unroll
            for (int d = 0; d < 8; d++) t += emb[d] * We[d * CC + j];
            t *= att_edge[l * CC + j];
        }
        for (int o = 16; o; o >>= 1) t += __shfl_xor_sync(FULL, t, o);
        __shared__ float rs[2];
        if (j == 0 || j == 32) rs[j >> 5] = t;
        __syncthreads();
        if (j == 0) d_relatt[l * RR + r] = rs[0] + rs[1];
    } else {
        float s1 = 0.f, s2 = 0.f;
        if (j < 64) {
            float cs = 0.f;
#pragma unroll
            for (int k = 0; k < CC; k++) cs += W[k * CC + j];
            d_colsum[j] = cs;
            s1 = cs * att_src[j];
            s2 = cs * att_dst[j];
        }
        for (int o = 16; o; o >>= 1) {
            s1 += __shfl_xor_sync(FULL, s1, o);
            s2 += __shfl_xor_sync(FULL, s2, o);
        }
        __shared__ float r1[2], r2[2];
        if (j == 0 || j == 32) { r1[j >> 5] = s1; r2[j >> 5] = s2; }
        __syncthreads();
        if (j == 0) { d_l0s[0] = r1[0] + r1[1]; d_l0s[1] = r2[0] + r2[1]; }
    }
}

// ---------------- CSR scan (shfl-based) ----------------
__global__ __launch_bounds__(1024) void k_scan1() {
    int tid = threadIdx.x;
    int i = blockIdx.x * 1024 + tid;
    int v = (i < NN) ? d_deg[i] : 0;
    if (i < NN) d_deg[i] = 0;                            // self-clean for next call
    int lane = tid & 31, w = tid >> 5;
    int sc = v;
#pragma unroll
    for (int o = 1; o < 32; o <<= 1) {
        int t = __shfl_up_sync(FULL, sc, o);
        if (lane >= o) sc += t;
    }
    __shared__ int wsum[32];
    if (lane == 31) wsum[w] = sc;
    __syncthreads();
    if (w == 0) {
        int x = wsum[lane];
#pragma unroll
        for (int o = 1; o < 32; o <<= 1) {
            int t = __shfl_up_sync(FULL, x, o);
            if (lane >= o) x += t;
        }
        wsum[lane] = x;
    }
    __syncthreads();
    int incl = sc + (w ? wsum[w - 1] : 0);
    if (i < NN) d_rowptr[i] = incl - v;                  // exclusive within block
    if (tid == 1023) d_bsum[blockIdx.x] = incl;          // block total
}

__global__ void k_scan2() {
    int tid = threadIdx.x;
    int v = (tid < NB_SCAN) ? d_bsum[tid] : 0;
    int orig = v;
    int lane = tid & 31, w = tid >> 5;
    for (int o = 1; o < 32; o <<= 1) {
        int t = __shfl_up_sync(FULL, v, o);
        if (lane >= o) v += t;
    }
    __shared__ int ws[4];
    if (lane == 31) ws[w] = v;
    __syncthreads();
    for (int k = 0; k < w; k++) v += ws[k];
    if (tid < NB_SCAN) d_bsum[tid] = v - orig;           // exclusive block offsets
}

__global__ void k_scan3() {
    int i = blockIdx.x * 1024 + threadIdx.x;
    if (i < NN) {
        d_rowptr[i] += d_bsum[blockIdx.x];
        d_cursor[i] = 0;                                 // clean before k_fill
    }
    if (i == 0) d_rowptr[NN] = EE;
}

__global__ void k_fill(const int* __restrict__ ei, const int* __restrict__ et) {
    int e = blockIdx.x * 256 + threadIdx.x;
    if (e < EE) {
        int s = ei[e];
        int d = ei[EE + e];
        int t = et[e];
        int pos = d_rowptr[d] + atomicAdd(&d_cursor[d], 1);
        d_adj[pos] = s | (t << 20);                      // src<2^20, type<32
    }
}

// ---- layer-0 aggregation: scalar softmax-weighted x gather, materialize h0 ----
__global__ __launch_bounds__(256) void k_agg0(const float* __restrict__ x,
                                              const float* __restrict__ bias) {
    __shared__ float rel_s[RR];
    __shared__ float cs_s[64], bi_s[64];
    __shared__ float red[8][2];
    int tid = threadIdx.x;
    if (tid < 64)                 cs_s[tid] = d_colsum[tid];
    else if (tid < 128)           bi_s[tid - 64] = bias[tid - 64];
    else if (tid < 128 + RR)      rel_s[tid - 128] = d_relatt[tid - 128];
    __syncthreads();
    float s0 = d_l0s[0], s1 = d_l0s[1];

    int wid  = (blockIdx.x * 256 + tid) >> 5;            // node id
    int lane = tid & 31;
    int start = d_rowptr[wid], end = d_rowptr[wid + 1];
    int deg = end - start;
    float xd = x[wid];
    float acc;

    if (deg <= 32) {
        int p = (lane < deg) ? d_adj[start + lane] : 0;
        float xs = (lane < deg) ? x[p & 0xFFFFF] : 0.f;
        float ex = 0.f;
        if (lane < deg) {
            float l = xs * s0 + xd * s1 + rel_s[p >> 20];
            l = (l > 0.f) ? l : 0.2f * l;
            ex = __expf(l);
        }
        float den = ex;
        float t = ex * xs;
        for (int o = 16; o; o >>= 1) {
            den += __shfl_xor_sync(FULL, den, o);
            t   += __shfl_xor_sync(FULL, t, o);
        }
        acc = __fdividef(t, den + 1e-16f);
    } else {
        float den = 0.f, num = 0.f;
        for (int i = start + lane; i < end; i += 32) {
            int p = d_adj[i];
            float xs = x[p & 0xFFFFF];
            float l = xs * s0 + xd * s1 + rel_s[p >> 20];
            l = (l > 0.f) ? l : 0.2f * l;
            float ex = __expf(l);
            den += ex;
            num += ex * xs;
        }
        for (int o = 16; o; o >>= 1) {
            den += __shfl_xor_sync(FULL, den, o);
            num += __shfl_xor_sync(FULL, num, o);
        }
        acc = __fdividef(num, den + 1e-16f);
    }

    // materialize h0 row: acc*colsum + bias  (exact fp32)
    int c = lane * 2;
    float ox = acc * cs_s[c]     + bi_s[c];
    float oy = acc * cs_s[c + 1] + bi_s[c + 1];
    *(float2*)&d_b0[wid * 64 + c] = make_float2(ox, oy);

    // fused LN partial reduction (block -> d_part)
    float s  = ox + oy;
    float ss = ox * ox + oy * oy;
    for (int o = 16; o; o >>= 1) {
        s  += __shfl_xor_sync(FULL, s, o);
        ss += __shfl_xor_sync(FULL, ss, o);
    }
    int w = tid >> 5;
    if (lane == 0) { red[w][0] = s; red[w][1] = ss; }
    __syncthreads();
    if (tid == 0) {
        float ts = 0.f, tss = 0.f;
#pragma unroll
        for (int k = 0; k < 8; k++) { ts += red[k][0]; tss += red[k][1]; }
        d_part[blockIdx.x * 2]     = ts;
        d_part[blockIdx.x * 2 + 1] = tss;
    }
}

// ---------------- HMMA helper ----------------
__device__ __forceinline__ void mma16816(float& c0, float& c1, float& c2, float& c3,
        unsigned a0, unsigned a1, unsigned a2, unsigned a3,
        unsigned b0, unsigned b1) {
    asm volatile(
        "mma.sync.aligned.m16n8k16.row.col.f32.f16.f16.f32 "
        "{%0,%1,%2,%3}, {%4,%5,%6,%7}, {%8,%9}, {%0,%1,%2,%3};\n"
        : "+f"(c0), "+f"(c1), "+f"(c2), "+f"(c3)
        : "r"(a0), "r"(a1), "r"(a2), "r"(a3), "r"(b0), "r"(b1));
}

// ---- hp = relu(norm(h_prev)) @ W  (HMMA, fp16 out) + alpha vectors (layers 1,2) ----
__global__ __launch_bounds__(256) void k_gemm_alpha(int layer,
        const float* __restrict__ Wl,
        const float* __restrict__ as_g, const float* __restrict__ ad_g,
        const float* __restrict__ lnw,  const float* __restrict__ lnb) {
    __shared__ __half As[128 * 72];
    __shared__ __half Wt[64 * 72];
    __shared__ float as_s[64], ad_s[64], Ak[64], Bk[64];
    int tid = threadIdx.x;
    for (int i = tid; i < 4096; i += 256) {              // Wt[n][k] = W[k][n]
        int k = i >> 6, n = i & 63;
        Wt[n * 72 + k] = __float2half(Wl[i]);
    }
    if (tid < 64) { as_s[tid] = as_g[tid]; ad_s[tid] = ad_g[tid]; }
    float mu  = d_stats[(layer - 1) * 2];
    float inv = d_stats[(layer - 1) * 2 + 1];
    if (tid < 64) {
        float g = lnw[tid];
        Ak[tid] = inv * g;
        Bk[tid] = lnb[tid] - mu * inv * g;
    }
    __syncthreads();

    const float* hin = buf(layer - 1);
    int base = blockIdx.x * 128;
    for (int i = tid; i < 4096; i += 256) {              // fill A (half2)
        int node = i >> 5, k2 = (i & 31) * 2;
        int gn = base + node;
        float v0 = 0.f, v1 = 0.f;
        if (gn < NN) {
            float2 r = *(const float2*)&hin[gn * 64 + k2];
            v0 = fmaxf(Ak[k2] * r.x + Bk[k2], 0.f);
            v1 = fmaxf(Ak[k2 + 1] * r.y + Bk[k2 + 1], 0.f);
        }
        *(__half2*)&As[node * 72 + k2] = __floats2half2_rn(v0, v1);
    }
    __syncthreads();

    int w = tid >> 5, lane = tid & 31;
    int gid = lane >> 2, t = lane & 3;
    int r0 = (w * 16 + gid) * 72;
    unsigned af[16];
#pragma unroll
    for (int kk = 0; kk < 4; kk++) {
        int bk = kk * 16 + 2 * t;
        af[kk * 4 + 0] = *(const unsigned*)&As[r0 + bk];
        af[kk * 4 + 1] = *(const unsigned*)&As[r0 + 8 * 72 + bk];
        af[kk * 4 + 2] = *(const unsigned*)&As[r0 + bk + 8];
        af[kk * 4 + 3] = *(const unsigned*)&As[r0 + 8 * 72 + bk + 8];
    }
    int rowA = base + w * 16 + gid, rowB = rowA + 8;
    float psl = 0.f, pdl = 0.f, psh = 0.f, pdh = 0.f;
#pragma unroll
    for (int nt = 0; nt < 8; nt++) {
        float c0 = 0.f, c1 = 0.f, c2 = 0.f, c3 = 0.f;
        int wrow = (nt * 8 + gid) * 72;
#pragma unroll
        for (int kk = 0; kk < 4; kk++) {
            unsigned b0 = *(const unsigned*)&Wt[wrow + kk * 16 + 2 * t];
            unsigned b1 = *(const unsigned*)&Wt[wrow + kk * 16 + 2 * t + 8];
            mma16816(c0, c1, c2, c3, af[kk*4], af[kk*4+1], af[kk*4+2], af[kk*4+3], b0, b1);
        }
        int col = nt * 8 + 2 * t;
        if (rowA < NN) d_hph[rowA * 32 + nt * 4 + t] = __floats2half2_rn(c0, c1);
        if (rowB < NN) d_hph[rowB * 32 + nt * 4 + t] = __floats2half2_rn(c2, c3);
        psl += c0 * as_s[col] + c1 * as_s[col + 1];
        pdl += c0 * ad_s[col] + c1 * ad_s[col + 1];
        psh += c2 * as_s[col] + c3 * as_s[col + 1];
        pdh += c2 * ad_s[col] + c3 * ad_s[col + 1];
    }
#pragma unroll
    for (int o = 1; o <= 2; o <<= 1) {
        psl += __shfl_xor_sync(FULL, psl, o);
        pdl += __shfl_xor_sync(FULL, pdl, o);
        psh += __shfl_xor_sync(FULL, psh, o);
        pdh += __shfl_xor_sync(FULL, pdh, o);
    }
    if (t == 0) {
        if (rowA < NN) { d_asrch[rowA] = __float2half(psl); d_adst[rowA] = pdl; }
        if (rowB < NN) { d_asrch[rowB] = __float2half(psh); d_adst[rowB] = pdh; }
    }
}

// ------- warp-per-dst GAT aggregation (quad-gather) + fused LN partials -------
__global__ __launch_bounds__(256) void k_agg(int layer, const float* __restrict__ bias,
                                             const float* __restrict__ lnw,
                                             const float* __restrict__ lnb) {
    __shared__ float rel_s[RR];
    __shared__ float lnw_s[64], lnb_s[64];
    __shared__ float red[8][2];
    int tid = threadIdx.x;
    if (tid < RR) rel_s[tid] = d_relatt[layer * RR + tid];
    if (tid >= 32 && tid < 96) {
        lnw_s[tid - 32] = lnw[tid - 32];
        lnb_s[tid - 32] = lnb[tid - 32];
    }
    __syncthreads();

    int wid  = (blockIdx.x * 256 + tid) >> 5;            // node id
    int lane = tid & 31;
    int start = d_rowptr[wid], end = d_rowptr[wid + 1];
    int deg = end - start;
    float ad = d_adst[wid];
    float a[8] = {0.f, 0.f, 0.f, 0.f, 0.f, 0.f, 0.f, 0.f};
    int g = lane >> 3, q = lane & 7;                     // lane group g, channel block q

    if (deg <= 32) {
        int p = (lane < deg) ? d_adj[start + lane] : 0;
        int s = p & 0xFFFFF;
        float ex = 0.f;
        if (lane < deg) {
            float l = __half2float(d_asrch[s]) + ad + rel_s[p >> 20];
            l = (l > 0.f) ? l : 0.2f * l;
            ex = __expf(l);
        }
        float den = ex;
        for (int o = 16; o; o >>= 1) den += __shfl_xor_sync(FULL, den, o);
        float coef = __fdividef(ex, den + 1e-16f);
        int nq = (deg + 3) >> 2;
        for (int i = 0; i < nq; i++) {
            int idx = 4 * i + g;                         // <=31
            float cf = __shfl_sync(FULL, coef, idx);     // 0 beyond deg
            int   si = __shfl_sync(FULL, s, idx);
            uint4 v = *(const uint4*)&d_hph[si * 32 + q * 4];
            float2 f0 = __half22float2(*(__half2*)&v.x);
            float2 f1 = __half22float2(*(__half2*)&v.y);
            float2 f2 = __half22float2(*(__half2*)&v.z);
            float2 f3 = __half22float2(*(__half2*)&v.w);
            a[0] += cf * f0.x; a[1] += cf * f0.y;
            a[2] += cf * f1.x; a[3] += cf * f1.y;
            a[4] += cf * f2.x; a[5] += cf * f2.y;
            a[6] += cf * f3.x; a[7] += cf * f3.y;
        }
#pragma unroll
        for (int j = 0; j < 8; j++) {
            a[j] += __shfl_xor_sync(FULL, a[j], 8);
            a[j] += __shfl_xor_sync(FULL, a[j], 16);
        }
    } else {
        float den = 0.f;
        for (int i = start + lane; i < end; i += 32) {
            int p = d_adj[i];
            float l = __half2float(d_asrch[p & 0xFFFFF]) + ad + rel_s[p >> 20];
            l = (l > 0.f) ? l : 0.2f * l;
            float ex = __expf(l);
            d_escratch[i] = ex;
            den += ex;
        }
        for (int o = 16; o; o >>= 1) den += __shfl_xor_sync(FULL, den, o);
        __syncwarp();
        float invd = __fdividef(1.f, den + 1e-16f);
        float ax = 0.f, ay = 0.f;                        // lane owns ch 2*lane, +1
        for (int i = start; i < end; i++) {
            int p = d_adj[i];
            float cf = d_escratch[i] * invd;
            float2 f = __half22float2(d_hph[(p & 0xFFFFF) * 32 + lane]);
            ax += cf * f.x;
            ay += cf * f.y;
        }
        // redistribute: channel 8q+2j from lane 4q+j
#pragma unroll
        for (int j = 0; j < 4; j++) {
            a[2 * j]     = __shfl_sync(FULL, ax, 4 * q + j);
            a[2 * j + 1] = __shfl_sync(FULL, ay, 4 * q + j);
        }
    }

    // epilogue: lanes 0-7 own channels 8q..8q+7; skip = relu(norm(prev))
    float o0 = 0.f, o1 = 0.f, o2 = 0.f, o3 = 0.f;
    float o4 = 0.f, o5 = 0.f, o6 = 0.f, o7 = 0.f;
    if (lane < 8) {
        int c = q * 8;
        const float* xl = buf(layer - 1);
        float pm = d_stats[(layer - 1) * 2], pi = d_stats[(layer - 1) * 2 + 1];
        float4 r0 = *(const float4*)&xl[wid * 64 + c];
        float4 r1 = *(const float4*)&xl[wid * 64 + c + 4];
        o0 = a[0] + bias[c]     + fmaxf((r0.x - pm) * pi * lnw_s[c]     + lnb_s[c],     0.f);
        o1 = a[1] + bias[c + 1] + fmaxf((r0.y - pm) * pi * lnw_s[c + 1] + lnb_s[c + 1], 0.f);
        o2 = a[2] + bias[c + 2] + fmaxf((r0.z - pm) * pi * lnw_s[c + 2] + lnb_s[c + 2], 0.f);
        o3 = a[3] + bias[c + 3] + fmaxf((r0.w - pm) * pi * lnw_s[c + 3] + lnb_s[c + 3], 0.f);
        o4 = a[4] + bias[c + 4] + fmaxf((r1.x - pm) * pi * lnw_s[c + 4] + lnb_s[c + 4], 0.f);
        o5 = a[5] + bias[c + 5] + fmaxf((r1.y - pm) * pi * lnw_s[c + 5] + lnb_s[c + 5], 0.f);
        o6 = a[6] + bias[c + 6] + fmaxf((r1.z - pm) * pi * lnw_s[c + 6] + lnb_s[c + 6], 0.f);
        o7 = a[7] + bias[c + 7] + fmaxf((r1.w - pm) * pi * lnw_s[c + 7] + lnb_s[c + 7], 0.f);
        float* hout = buf(layer);
        *(float4*)&hout[wid * 64 + c]     = make_float4(o0, o1, o2, o3);
        *(float4*)&hout[wid * 64 + c + 4] = make_float4(o4, o5, o6, o7);
    }

    // fused LN partial reduction (block -> d_part)
    float s  = o0 + o1 + o2 + o3 + o4 + o5 + o6 + o7;
    float ss = o0 * o0 + o1 * o1 + o2 * o2 + o3 * o3
             + o4 * o4 + o5 * o5 + o6 * o6 + o7 * o7;
    for (int o = 16; o; o >>= 1) {
        s  += __shfl_xor_sync(FULL, s, o);
        ss += __shfl_xor_sync(FULL, ss, o);
    }
    int w = tid >> 5;
    if (lane == 0) { red[w][0] = s; red[w][1] = ss; }
    __syncthreads();
    if (tid == 0) {
        float ts = 0.f, tss = 0.f;
#pragma unroll
        for (int k = 0; k < 8; k++) { ts += red[k][0]; tss += red[k][1]; }
        d_part[blockIdx.x * 2]     = ts;
        d_part[blockIdx.x * 2 + 1] = tss;
    }
}

// ---------------- LN finisher: combine 12500 partials ----------------
__global__ void k_lnfin(int layer) {
    int tid = threadIdx.x;                               // 1024 threads
    float s = 0.f, ss = 0.f;
    for (int i = tid; i < NAGG_BLK; i += 1024) {
        s  += d_part[2 * i];
        ss += d_part[2 * i + 1];
    }
    for (int o = 16; o; o >>= 1) {
        s  += __shfl_xor_sync(FULL, s, o);
        ss += __shfl_xor_sync(FULL, ss, o);
    }
    __shared__ float sh[32][2];
    int w = tid >> 5, lane = tid & 31;
    if (lane == 0) { sh[w][0] = s; sh[w][1] = ss; }
    __syncthreads();
    if (w == 0) {
        s  = sh[lane][0];
        ss = sh[lane][1];
        for (int o = 16; o; o >>= 1) {
            s  += __shfl_xor_sync(FULL, s, o);
            ss += __shfl_xor_sync(FULL, ss, o);
        }
        if (lane == 0) {
            const float M = (float)NN * (float)CC;
            float mu  = s / M;
            float var = ss / M - mu * mu;
            var = var > 0.f ? var : 0.f;
            d_stats[layer * 2]     = mu;
            d_stats[layer * 2 + 1] = 1.f / (sqrtf(var) + 1e-5f);
        }
    }
}

// ---------------- MLP head via HMMA (norm fused on load) + sigmoid ----------------
__global__ __launch_bounds__(256) void k_mlp(const float* __restrict__ w1,
        const float* __restrict__ b1g, const float* __restrict__ w2,
        const float* __restrict__ b2,
        const float* __restrict__ lnw, const float* __restrict__ lnb,
        float* __restrict__ out) {
    __shared__ __half As[128 * 72];
    __shared__ __half Wt[104 * 72];
    __shared__ float b1s[104], w2s[104], Ak[64], Bk[64];
    int tid = threadIdx.x;
    for (int i = tid; i < 104 * 72; i += 256) Wt[i] = __float2half(0.f);
    if (tid < 104) {
        b1s[tid] = (tid < 100) ? b1g[tid] : 0.f;
        w2s[tid] = (tid < 100) ? w2[tid] : 0.f;
    }
    __syncthreads();
    for (int i = tid; i < 6400; i += 256) {              // Wt[n][k] = w1[k][n]
        int k = i / 100, n = i % 100;
        Wt[n * 72 + k] = __float2half(w1[i]);
    }
    float mu = d_stats[4], inv = d_stats[5];
    if (tid < 64) {
        float g = lnw[tid];
        Ak[tid] = inv * g;
        Bk[tid] = lnb[tid] - mu * inv * g;
    }
    __syncthreads();

    int base = blockIdx.x * 128;
    for (int i = tid; i < 4096; i += 256) {
        int node = i >> 5, k2 = (i & 31) * 2;
        int gn = base + node;
        float v0 = 0.f, v1 = 0.f;
        if (gn < NN) {
            float2 r = *(const float2*)&d_b2[gn * 64 + k2];
            v0 = fmaxf(Ak[k2] * r.x + Bk[k2], 0.f);
            v1 = fmaxf(Ak[k2 + 1] * r.y + Bk[k2 + 1], 0.f);
        }
        *(__half2*)&As[node * 72 + k2] = __floats2half2_rn(v0, v1);
    }
    __syncthreads();

    int w = tid >> 5, lane = tid & 31;
    int gid = lane >> 2, t = lane & 3;
    int r0 = (w * 16 + gid) * 72;
    unsigned af[16];
#pragma unroll
    for (int kk = 0; kk < 4; kk++) {
        int bk = kk * 16 + 2 * t;
        af[kk * 4 + 0] = *(const unsigned*)&As[r0 + bk];
        af[kk * 4 + 1] = *(const unsigned*)&As[r0 + 8 * 72 + bk];
        af[kk * 4 + 2] = *(const unsigned*)&As[r0 + bk + 8];
        af[kk * 4 + 3] = *(const unsigned*)&As[r0 + 8 * 72 + bk + 8];
    }
    float zl = 0.f, zh = 0.f;
#pragma unroll
    for (int nt = 0; nt < 13; nt++) {
        float c0 = 0.f, c1 = 0.f, c2 = 0.f, c3 = 0.f;
        int wrow = (nt * 8 + gid) * 72;
#pragma unroll
        for (int kk = 0; kk < 4; kk++) {
            unsigned b0 = *(const unsigned*)&Wt[wrow + kk * 16 + 2 * t];
            unsigned b1 = *(const unsigned*)&Wt[wrow + kk * 16 + 2 * t + 8];
            mma16816(c0, c1, c2, c3, af[kk*4], af[kk*4+1], af[kk*4+2], af[kk*4+3], b0, b1);
        }
        int col = nt * 8 + 2 * t;
        zl += fmaxf(c0 + b1s[col], 0.f) * w2s[col] + fmaxf(c1 + b1s[col + 1], 0.f) * w2s[col + 1];
        zh += fmaxf(c2 + b1s[col], 0.f) * w2s[col] + fmaxf(c3 + b1s[col + 1], 0.f) * w2s[col + 1];
    }
#pragma unroll
    for (int o = 1; o <= 2; o <<= 1) {
        zl += __shfl_xor_sync(FULL, zl, o);
        zh += __shfl_xor_sync(FULL, zh, o);
    }
    if (t == 0) {
        float bb = b2[0];
        int rowA = base + w * 16 + gid, rowB = rowA + 8;
        if (rowA < NN) out[rowA] = 1.f / (1.f + __expf(-(zl + bb)));
        if (rowB < NN) out[rowB] = 1.f / (1.f + __expf(-(zh + bb)));
    }
}

// ---------------- launch ----------------
extern "C" void kernel_launch(void* const* d_in, const int* in_sizes, int n_in,
                              void* d_out, int out_size) {
    const float* x         = (const float*)d_in[0];
    const int*   ei        = (const int*)  d_in[1];
    const int*   et        = (const int*)  d_in[2];
    const float* W         = (const float*)d_in[3];
    const float* att_src   = (const float*)d_in[4];
    const float* att_dst   = (const float*)d_in[5];
    const float* lin_edge  = (const float*)d_in[6];
    const float* att_edge  = (const float*)d_in[7];
    const float* conv_bias = (const float*)d_in[8];
    const float* edge_emb  = (const float*)d_in[9];
    const float* ln_w      = (const float*)d_in[10];
    const float* ln_b      = (const float*)d_in[11];
    const float* w1        = (const float*)d_in[12];
    const float* b1        = (const float*)d_in[13];
    const float* w2        = (const float*)d_in[14];
    const float* b2        = (const float*)d_in[15];
    float* out = (float*)d_out;

    // CSR build + relprep (deg/cursor are self-cleaning across calls)
    k_degrel<<<DEG_BLOCKS + LL * RR + 1, 256>>>(ei, lin_edge, att_edge, edge_emb,
                                                W, att_src, att_dst);
    k_scan1<<<NB_SCAN, 1024>>>();
    k_scan2<<<1, 128>>>();
    k_scan3<<<NB_SCAN, 1024>>>();
    k_fill<<<EE / 256, 256>>>(ei, et);

    k_agg0<<<NAGG_BLK, 256>>>(x, conv_bias);
    k_lnfin<<<1, 1024>>>(0);
    for (int l = 1; l < LL; l++) {
        k_gemm_alpha<<<(NN + 127) / 128, 256>>>(l, W + l * CC * CC,
                                                att_src + l * CC, att_dst + l * CC,
                                                ln_w, ln_b);
        k_agg<<<NAGG_BLK, 256>>>(l, conv_bias + l * CC, ln_w, ln_b);
        k_lnfin<<<1, 1024>>>(l);
    }
    k_mlp<<<(NN + 127) / 128, 256>>>(w1, b1, w2, b2, ln_w, ln_b, out);
}